// round 13
// baseline (speedup 1.0000x reference)
#include <cuda_runtime.h>
#include <math.h>

#define BATCH 8
#define CCH   256
#define HH    64
#define WW    64
#define NN    4096   // HH*WW
#define MM    1024   // (HH/2)*(WW/2)
#define HK    32
#define WK    32

typedef unsigned long long u64;
typedef unsigned int u32;

// pack (lo, hi) floats -> bf16x2 word (lo in low half)
__device__ __forceinline__ u32 pkbf(float lo, float hi) {
    u32 d; asm("cvt.rn.bf16x2.f32 %0,%1,%2;" : "=r"(d) : "f"(hi), "f"(lo)); return d;
}
__device__ __forceinline__ void mma_bf16(float* d, const u32* a, const u32* b) {
    asm volatile(
        "mma.sync.aligned.m16n8k16.row.col.f32.bf16.bf16.f32 "
        "{%0,%1,%2,%3},{%4,%5,%6,%7},{%8,%9},{%0,%1,%2,%3};"
        : "+f"(d[0]), "+f"(d[1]), "+f"(d[2]), "+f"(d[3])
        : "r"(a[0]), "r"(a[1]), "r"(a[2]), "r"(a[3]), "r"(b[0]), "r"(b[1]));
}

// Scratch
__device__ float g_q[(size_t)BATCH * CCH * NN];   // 32 MB
__device__ float g_k[(size_t)BATCH * CCH * MM];   // 8 MB
__device__ float g_v[(size_t)BATCH * CCH * MM];   // 8 MB
__device__ float g_e[(size_t)BATCH * NN * MM];    // 128 MB (pre-softmax, fp32)
__device__ u32   g_a[(size_t)BATCH * NN * (MM/2)]; // 64 MB (post-softmax, bf16x2)
__device__ u32   g_xp[(size_t)BATCH * 128 * NN];  // 16 MB (x packed bf16x2)
__device__ u32   g_yp[(size_t)BATCH * 128 * NN];  // 16 MB (y packed bf16x2)
__device__ u32   g_wt3[9 * 128 * 256];            // Wq [k][ci2][co] bf16x2
__device__ u32   g_wk3[4 * 128 * 256];            // Wk [k][ci2][co] bf16x2
__device__ u32   g_wv3[4 * 128 * 256];            // Wv [k][ci2][co] bf16x2

// ---------------------------------------------------------------------------
// Pack fp32 [b][ci][hw] -> bf16x2 [b][ci2][hw] (ci pairs). Used for x and y.
// ---------------------------------------------------------------------------
__global__ __launch_bounds__(256) void xpack_kernel(
    const float* __restrict__ x, u32* __restrict__ xp)
{
    size_t i = (size_t)blockIdx.x * 256 + threadIdx.x;
    if (i < (size_t)BATCH * 128 * NN) {
        int hw  = i & (NN - 1);
        int c2  = (i >> 12) & 127;
        int b   = i >> 19;
        size_t base = ((size_t)b * CCH + 2 * c2) * NN + hw;
        xp[i] = pkbf(x[base], x[base + NN]);
    }
}

// ---------------------------------------------------------------------------
// Wq OIHW -> [k][ci2][co] packed bf16x2.
// ---------------------------------------------------------------------------
__global__ __launch_bounds__(256) void transpose_w3(
    const float* __restrict__ Wt, u32* __restrict__ wt3)
{
    int i = blockIdx.x * 256 + threadIdx.x;
    if (i < 9 * 128 * 256) {
        int co  = i & 255;
        int ci2 = (i >> 8) & 127;
        int k   = i >> 15;
        float lo = Wt[((size_t)co * 256 + 2 * ci2) * 9 + k];
        float hi = Wt[((size_t)co * 256 + 2 * ci2 + 1) * 9 + k];
        wt3[i] = pkbf(lo, hi);
    }
}

// Wk/Wv OIHW -> [k][ci2][co] packed bf16x2.
__global__ __launch_bounds__(256) void transpose_w2(
    const float* __restrict__ Wk, const float* __restrict__ Wv,
    u32* __restrict__ wk3, u32* __restrict__ wv3)
{
    int i = blockIdx.x * 256 + threadIdx.x;
    if (i < 4 * 128 * 256) {
        int co  = i & 255;
        int ci2 = (i >> 8) & 127;
        int k   = i >> 15;
        float klo = Wk[((size_t)co * 256 + 2 * ci2) * 4 + k];
        float khi = Wk[((size_t)co * 256 + 2 * ci2 + 1) * 4 + k];
        wk3[i] = pkbf(klo, khi);
        float vlo = Wv[((size_t)co * 256 + 2 * ci2) * 4 + k];
        float vhi = Wv[((size_t)co * 256 + 2 * ci2 + 1) * 4 + k];
        wv3[i] = pkbf(vlo, vhi);
    }
}

// ---------------------------------------------------------------------------
// 3x3 conv s1 p1, implicit GEMM bf16, input from packed xp, uint4 staging.
// grid: (HH/2=32, CCH/64=4, B=8)
// ---------------------------------------------------------------------------
__global__ __launch_bounds__(256, 2) void conv3_mma(
    const u32* __restrict__ wt3, const u32* __restrict__ xp,
    const float* __restrict__ bias, float* __restrict__ out)
{
    const int h0  = blockIdx.x * 2;
    const int co0 = blockIdx.y * 64;
    const int b   = blockIdx.z;
    const int tid  = threadIdx.x;
    const int lane = tid & 31;
    const int w    = tid >> 5;
    const int gid  = lane >> 2;
    const int ctid = lane & 3;
    const int co_base = (w >> 2) * 32;
    const int px_base = (w & 3) * 32;

    __shared__ u32 sxt[4 * 8 * 72];   // [r][c2][col pad 72]; col = gw+1
    __shared__ u32 swt[8 * 9 * 72];   // [c2][k][co pad 72]

    float acc[2][4][4];
#pragma unroll
    for (int i = 0; i < 2; i++)
#pragma unroll
        for (int j = 0; j < 4; j++)
#pragma unroll
            for (int l = 0; l < 4; l++) acc[i][j][l] = 0.f;

    const u32* xpb = xp + (size_t)b * 128 * NN;

    if (tid < 64) {
        int r  = tid >> 4;
        int c2 = (tid >> 1) & 7;
        int side = tid & 1;
        sxt[(r * 8 + c2) * 72 + side * 65] = 0;
    }

    uint4 pin[2], pin2[2];

#define C3_LOAD(dst, CI0)                                                    \
    {                                                                        \
        _Pragma("unroll")                                                    \
        for (int j = 0; j < 2; j++) {                                        \
            int idx = tid + j * 256;                                         \
            int r  = idx >> 7;                                               \
            int c2 = (idx >> 4) & 7;                                         \
            int q  = idx & 15;                                               \
            int gh = h0 - 1 + r;                                             \
            uint4 v = {0u, 0u, 0u, 0u};                                      \
            if ((unsigned)gh < HH)                                           \
                v = *reinterpret_cast<const uint4*>(                         \
                    &xpb[(size_t)(((CI0) >> 1) + c2) * NN + gh * WW + q * 4]);\
            dst[j] = v;                                                      \
        }                                                                    \
    }

    C3_LOAD(pin, 0);

    for (int ci0 = 0; ci0 < CCH; ci0 += 16) {
#pragma unroll
        for (int j = 0; j < 2; j++) {
            int idx = tid + j * 256;
            int r  = idx >> 7;
            int c2 = (idx >> 4) & 7;
            int q  = idx & 15;
            u32* d = &sxt[(r * 8 + c2) * 72 + 1 + q * 4];
            d[0] = pin[j].x; d[1] = pin[j].y; d[2] = pin[j].z; d[3] = pin[j].w;
        }
        for (int i = tid; i < 8 * 9 * 16; i += 256) {
            int k   = i / 128;
            int c2  = (i >> 4) & 7;
            int co4 = (i & 15) * 4;
            uint4 v = *reinterpret_cast<const uint4*>(
                &wt3[((size_t)k * 128 + (ci0 >> 1) + c2) * 256 + co0 + co4]);
            *reinterpret_cast<uint4*>(&swt[(c2 * 9 + k) * 72 + co4]) = v;
        }
        __syncthreads();

        if (ci0 + 16 < CCH) C3_LOAD(pin2, ci0 + 16);

#pragma unroll
        for (int k = 0; k < 9; k++) {
            const int kh = k / 3, kw = k % 3;
            u32 a[2][4];
#pragma unroll
            for (int rm = 0; rm < 2; rm++) {
                int cof = co_base + rm * 16;
                a[rm][0] = swt[((ctid) * 9 + k) * 72 + cof + gid];
                a[rm][1] = swt[((ctid) * 9 + k) * 72 + cof + gid + 8];
                a[rm][2] = swt[((ctid + 4) * 9 + k) * 72 + cof + gid];
                a[rm][3] = swt[((ctid + 4) * 9 + k) * 72 + cof + gid + 8];
            }
#pragma unroll
            for (int f = 0; f < 4; f++) {
                int px = px_base + f * 8 + gid;
                int rl = px >> 6;
                int wc = (px & 63) + kw;
                u32 bf[2];
                bf[0] = sxt[((rl + kh) * 8 + ctid) * 72 + wc];
                bf[1] = sxt[((rl + kh) * 8 + ctid + 4) * 72 + wc];
                mma_bf16(acc[0][f], a[0], bf);
                mma_bf16(acc[1][f], a[1], bf);
            }
        }
        __syncthreads();

        pin[0] = pin2[0]; pin[1] = pin2[1];
    }

#pragma unroll
    for (int rm = 0; rm < 2; rm++) {
#pragma unroll
        for (int f = 0; f < 4; f++) {
            int coA = co0 + co_base + rm * 16 + gid;
            int coB = coA + 8;
            int px  = px_base + f * 8 + 2 * ctid;
            int n   = (h0 + (px >> 6)) * WW + (px & 63);
            float bA = bias[coA], bB = bias[coB];
            float2 sA = {acc[rm][f][0] + bA, acc[rm][f][1] + bA};
            float2 sB = {acc[rm][f][2] + bB, acc[rm][f][3] + bB};
            *reinterpret_cast<float2*>(&out[((size_t)b * CCH + coA) * NN + n]) = sA;
            *reinterpret_cast<float2*>(&out[((size_t)b * CCH + coB) * NN + n]) = sB;
        }
    }
}

// ---------------------------------------------------------------------------
// FUSED K+V 2x2 conv s2 p0, implicit GEMM bf16 (m16n8k16), ci-chunk 16,
// input from packed yp, prefetched. grid: (HK/4=8, CCH/64=4, B=8)
// ---------------------------------------------------------------------------
__global__ __launch_bounds__(256, 2) void conv2kv_mma(
    const u32* __restrict__ wtK, const u32* __restrict__ wtV,
    const u32* __restrict__ yp,
    const float* __restrict__ bK, const float* __restrict__ bV,
    float* __restrict__ outK, float* __restrict__ outV)
{
    const int h0  = blockIdx.x * 4;
    const int co0 = blockIdx.y * 64;
    const int b   = blockIdx.z;
    const int tid  = threadIdx.x;
    const int lane = tid & 31;
    const int w    = tid >> 5;
    const int gid  = lane >> 2;
    const int ctid = lane & 3;
    const int co_base = (w >> 2) * 32;
    const int px_base = (w & 3) * 32;

    __shared__ u32 sy[2 * 8 * 8 * 40];   // [kw][r][ci2][w/2 pad 40] bf16x2
    __shared__ u32 swK[8 * 4 * 74];      // [ci2][k][co pad 74] bf16x2
    __shared__ u32 swV[8 * 4 * 74];

    float accK[2][4][4], accV[2][4][4];
#pragma unroll
    for (int i = 0; i < 2; i++)
#pragma unroll
        for (int j = 0; j < 4; j++)
#pragma unroll
            for (int l = 0; l < 4; l++) { accK[i][j][l] = 0.f; accV[i][j][l] = 0.f; }

    const u32* ypb = yp + (size_t)b * 128 * NN;
    const int ih0 = h0 * 2;

    uint4 pin[4], pin2[4];

#define C2_LOAD(dst, CI0)                                                    \
    {                                                                        \
        _Pragma("unroll")                                                    \
        for (int j = 0; j < 4; j++) {                                        \
            int i   = tid + j * 256;                                         \
            int r   = i >> 7;                                                \
            int ci2 = (i >> 4) & 7;                                          \
            int c4  = i & 15;                                                \
            dst[j] = *reinterpret_cast<const uint4*>(                        \
                &ypb[(size_t)(((CI0) >> 1) + ci2) * NN + (ih0 + r) * WW + c4 * 4]); \
        }                                                                    \
    }

    C2_LOAD(pin, 0);

    for (int ci0 = 0; ci0 < CCH; ci0 += 16) {
        // stage input (parity split on w)
#pragma unroll
        for (int j = 0; j < 4; j++) {
            int i   = tid + j * 256;
            int r   = i >> 7;
            int ci2 = (i >> 4) & 7;
            int c4  = i & 15;
            u32* even = &sy[((0 * 8 + r) * 8 + ci2) * 40 + c4 * 2];
            u32* odd  = &sy[((8 + r) * 8 + ci2) * 40 + c4 * 2];
            even[0] = pin[j].x; odd[0] = pin[j].y;
            even[1] = pin[j].z; odd[1] = pin[j].w;
        }
        // stage both weight sets (scalar stores: stride 74 not 16B-aligned)
        for (int i = tid; i < 8 * 4 * 16; i += 256) {
            int k   = i / 128;
            int ci2 = (i >> 4) & 7;
            int co4 = (i & 15) * 4;
            size_t off = ((size_t)k * 128 + (ci0 >> 1) + ci2) * 256 + co0 + co4;
            uint4 vk = *reinterpret_cast<const uint4*>(&wtK[off]);
            uint4 vv = *reinterpret_cast<const uint4*>(&wtV[off]);
            u32* dk = &swK[(ci2 * 4 + k) * 74 + co4];
            dk[0] = vk.x; dk[1] = vk.y; dk[2] = vk.z; dk[3] = vk.w;
            u32* dv = &swV[(ci2 * 4 + k) * 74 + co4];
            dv[0] = vv.x; dv[1] = vv.y; dv[2] = vv.z; dv[3] = vv.w;
        }
        __syncthreads();

        if (ci0 + 16 < CCH) C2_LOAD(pin2, ci0 + 16);

#pragma unroll
        for (int k = 0; k < 4; k++) {
            const int kh = k >> 1, kw = k & 1;
            u32 aK[2][4], aV[2][4];
#pragma unroll
            for (int rm = 0; rm < 2; rm++) {
                int cof = co_base + rm * 16;
                int r0 = (ctid * 4 + k) * 74 + cof;
                int r1 = ((ctid + 4) * 4 + k) * 74 + cof;
                aK[rm][0] = swK[r0 + gid];     aK[rm][1] = swK[r0 + gid + 8];
                aK[rm][2] = swK[r1 + gid];     aK[rm][3] = swK[r1 + gid + 8];
                aV[rm][0] = swV[r0 + gid];     aV[rm][1] = swV[r0 + gid + 8];
                aV[rm][2] = swV[r1 + gid];     aV[rm][3] = swV[r1 + gid + 8];
            }
#pragma unroll
            for (int f = 0; f < 4; f++) {
                int px = px_base + f * 8 + gid;
                int r  = 2 * (px >> 5) + kh;
                int wl = px & 31;
                u32 bf[2];
                bf[0] = sy[((kw * 8 + r) * 8 + ctid) * 40 + wl];
                bf[1] = sy[((kw * 8 + r) * 8 + ctid + 4) * 40 + wl];
                mma_bf16(accK[0][f], aK[0], bf);
                mma_bf16(accK[1][f], aK[1], bf);
                mma_bf16(accV[0][f], aV[0], bf);
                mma_bf16(accV[1][f], aV[1], bf);
            }
        }
        __syncthreads();

#pragma unroll
        for (int j = 0; j < 4; j++) pin[j] = pin2[j];
    }

#pragma unroll
    for (int rm = 0; rm < 2; rm++) {
#pragma unroll
        for (int f = 0; f < 4; f++) {
            int coA = co0 + co_base + rm * 16 + gid;
            int coB = coA + 8;
            int px  = px_base + f * 8 + 2 * ctid;
            int n   = (h0 + (px >> 5)) * WK + (px & 31);
            size_t oA = ((size_t)b * CCH + coA) * MM + n;
            size_t oB = ((size_t)b * CCH + coB) * MM + n;
            float bkA = bK[coA], bkB = bK[coB];
            float bvA = bV[coA], bvB = bV[coB];
            float2 kA = {accK[rm][f][0] + bkA, accK[rm][f][1] + bkA};
            float2 kB = {accK[rm][f][2] + bkB, accK[rm][f][3] + bkB};
            float2 vA = {accV[rm][f][0] + bvA, accV[rm][f][1] + bvA};
            float2 vB = {accV[rm][f][2] + bvB, accV[rm][f][3] + bvB};
            *reinterpret_cast<float2*>(&outK[oA]) = kA;
            *reinterpret_cast<float2*>(&outK[oB]) = kB;
            *reinterpret_cast<float2*>(&outV[oA]) = vA;
            *reinterpret_cast<float2*>(&outV[oB]) = vB;
        }
    }
}

// ---------------------------------------------------------------------------
// GroupNorm(32 groups of 8 ch) + affine + SiLU, in place. float4, 512 thr.
// ---------------------------------------------------------------------------
__global__ __launch_bounds__(512) void gn_silu_kernel(
    float* __restrict__ buf, const float* __restrict__ scale,
    const float* __restrict__ bias, int S)
{
    const int b = blockIdx.x >> 5;
    const int g = blockIdx.x & 31;
    float* base = buf + ((size_t)b * CCH + g * 8) * S;
    float4* p4 = reinterpret_cast<float4*>(base);
    const int tot4 = (8 * S) >> 2;
    const int tid = threadIdx.x;

    float s = 0.f, ss = 0.f;
    for (int i = tid; i < tot4; i += 512) {
        float4 v = p4[i];
        s += v.x + v.y + v.z + v.w;
        ss = fmaf(v.x, v.x, ss);
        ss = fmaf(v.y, v.y, ss);
        ss = fmaf(v.z, v.z, ss);
        ss = fmaf(v.w, v.w, ss);
    }
    __shared__ float r1[512], r2[512];
    r1[tid] = s; r2[tid] = ss;
    __syncthreads();
    for (int st = 256; st > 0; st >>= 1) {
        if (tid < st) { r1[tid] += r1[tid + st]; r2[tid] += r2[tid + st]; }
        __syncthreads();
    }
    const float tot = (float)(8 * S);
    const float mu   = r1[0] / tot;
    const float var  = r2[0] / tot - mu * mu;
    const float rstd = rsqrtf(var + 1e-5f);

    const int s4 = S >> 2;
    for (int i = tid; i < tot4; i += 512) {
        int c = g * 8 + i / s4;
        float sc = scale[c] * rstd, bi = bias[c] - mu * scale[c] * rstd;
        float4 v = p4[i];
        v.x = fmaf(v.x, sc, bi);
        v.y = fmaf(v.y, sc, bi);
        v.z = fmaf(v.z, sc, bi);
        v.w = fmaf(v.w, sc, bi);
        v.x = v.x / (1.f + __expf(-v.x));
        v.y = v.y / (1.f + __expf(-v.y));
        v.z = v.z / (1.f + __expf(-v.z));
        v.w = v.w / (1.f + __expf(-v.w));
        p4[i] = v;
    }
}

// ---------------------------------------------------------------------------
// E = (1/16) Q^T K  (bf16 m16n8k16), staged loads double-buffered.
// grid: (MM/128=8, NN/128=32, B=8)
// ---------------------------------------------------------------------------
__global__ __launch_bounds__(256, 2) void gemm_qk_mma(
    const float* __restrict__ Q, const float* __restrict__ K,
    float* __restrict__ E)
{
    const int mb = blockIdx.x * 128;
    const int nb = blockIdx.y * 128;
    const int b  = blockIdx.z;
    const int tid  = threadIdx.x;
    const int lane = tid & 31;
    const int w    = tid >> 5;
    const int gid  = lane >> 2;
    const int ctid = lane & 3;
    const int m_base = (w & 1) * 64;
    const int n_base = (w >> 1) * 32;

    __shared__ u32 sq2[8 * 136];
    __shared__ u32 sk2[8 * 136];

    float acc[2][8][4];
#pragma unroll
    for (int i = 0; i < 2; i++)
#pragma unroll
        for (int j = 0; j < 8; j++)
#pragma unroll
            for (int l = 0; l < 4; l++) acc[i][j][l] = 0.f;

    const float* Qb = Q + (size_t)b * CCH * NN + nb;
    const float* Kb = K + (size_t)b * CCH * MM + mb;

    const int kc  = tid >> 5;
    const int col = (lane) * 4;

    float4 pq0, pq1, pk0, pk1, nq0, nq1, nk0, nk1;

#define QK_LOAD(q0, q1, k0, k1, C0)                                                        \
    {                                                                                      \
        q0 = *reinterpret_cast<const float4*>(&Qb[(size_t)((C0) + 2 * kc) * NN + col]);     \
        q1 = *reinterpret_cast<const float4*>(&Qb[(size_t)((C0) + 2 * kc + 1) * NN + col]); \
        k0 = *reinterpret_cast<const float4*>(&Kb[(size_t)((C0) + 2 * kc) * MM + col]);     \
        k1 = *reinterpret_cast<const float4*>(&Kb[(size_t)((C0) + 2 * kc + 1) * MM + col]); \
    }

    QK_LOAD(pq0, pq1, pk0, pk1, 0);

    for (int c0 = 0; c0 < CCH; c0 += 16) {
        uint4 qs = {pkbf(pq0.x, pq1.x), pkbf(pq0.y, pq1.y),
                    pkbf(pq0.z, pq1.z), pkbf(pq0.w, pq1.w)};
        uint4 ks = {pkbf(pk0.x, pk1.x), pkbf(pk0.y, pk1.y),
                    pkbf(pk0.z, pk1.z), pkbf(pk0.w, pk1.w)};
        *reinterpret_cast<uint4*>(&sq2[kc * 136 + col]) = qs;
        *reinterpret_cast<uint4*>(&sk2[kc * 136 + col]) = ks;
        __syncthreads();

        if (c0 + 16 < CCH) QK_LOAD(nq0, nq1, nk0, nk1, c0 + 16);

        u32 a[2][4];
#pragma unroll
        for (int rm = 0; rm < 2; rm++) {
            int n0 = n_base + rm * 16;
            a[rm][0] = sq2[ctid * 136 + n0 + gid];
            a[rm][1] = sq2[ctid * 136 + n0 + gid + 8];
            a[rm][2] = sq2[(ctid + 4) * 136 + n0 + gid];
            a[rm][3] = sq2[(ctid + 4) * 136 + n0 + gid + 8];
        }
#pragma unroll
        for (int f = 0; f < 8; f++) {
            u32 bf[2];
            bf[0] = sk2[ctid * 136 + m_base + f * 8 + gid];
            bf[1] = sk2[(ctid + 4) * 136 + m_base + f * 8 + gid];
            mma_bf16(acc[0][f], a[0], bf);
            mma_bf16(acc[1][f], a[1], bf);
        }
        __syncthreads();

        pq0 = nq0; pq1 = nq1; pk0 = nk0; pk1 = nk1;
    }

    const float scale = 0.0625f;
    float* Eb = E + ((size_t)b * NN + nb) * MM + mb;
#pragma unroll
    for (int rm = 0; rm < 2; rm++) {
#pragma unroll
        for (int f = 0; f < 8; f++) {
            int r0 = n_base + rm * 16 + gid;
            int cc = m_base + f * 8 + 2 * ctid;
            float2 s0 = {acc[rm][f][0] * scale, acc[rm][f][1] * scale};
            float2 s1 = {acc[rm][f][2] * scale, acc[rm][f][3] * scale};
            *reinterpret_cast<float2*>(&Eb[(size_t)r0 * MM + cc])       = s0;
            *reinterpret_cast<float2*>(&Eb[(size_t)(r0 + 8) * MM + cc]) = s1;
        }
    }
}

// ---------------------------------------------------------------------------
// Softmax over last dim (M=1024), fp32 in -> packed bf16x2 out (m-pairs).
// One WARP per row. grid: B*NN/8 = 4096.
// ---------------------------------------------------------------------------
__global__ __launch_bounds__(256) void softmax_kernel(
    const float* __restrict__ E, u32* __restrict__ A)
{
    const int warp = threadIdx.x >> 5;
    const int lane = threadIdx.x & 31;
    const size_t row = (size_t)blockIdx.x * 8 + warp;
    const float4* p = reinterpret_cast<const float4*>(E + row * MM);
    u32* pa = A + row * (MM / 2);

    float4 v[8];
    float mx = -1e30f;
#pragma unroll
    for (int i = 0; i < 8; i++) {
        v[i] = p[lane + 32 * i];
        mx = fmaxf(mx, fmaxf(fmaxf(v[i].x, v[i].y), fmaxf(v[i].z, v[i].w)));
    }
#pragma unroll
    for (int o = 16; o > 0; o >>= 1)
        mx = fmaxf(mx, __shfl_xor_sync(0xFFFFFFFFu, mx, o));

    float sum = 0.f;
#pragma unroll
    for (int i = 0; i < 8; i++) {
        v[i].x = __expf(v[i].x - mx);
        v[i].y = __expf(v[i].y - mx);
        v[i].z = __expf(v[i].z - mx);
        v[i].w = __expf(v[i].w - mx);
        sum += v[i].x + v[i].y + v[i].z + v[i].w;
    }
#pragma unroll
    for (int o = 16; o > 0; o >>= 1)
        sum += __shfl_xor_sync(0xFFFFFFFFu, sum, o);

    float inv = 1.f / sum;
#pragma unroll
    for (int i = 0; i < 8; i++) {
        uint2 st;
        st.x = pkbf(v[i].x * inv, v[i].y * inv);
        st.y = pkbf(v[i].z * inv, v[i].w * inv);
        *reinterpret_cast<uint2*>(&pa[2 * (lane + 32 * i)]) = st;
    }
}

// ---------------------------------------------------------------------------
// out = gamma * V A^T (bf16 m16n8k16). A read pre-packed bf16x2 (m-pairs).
// grid: (NN/128=32, CCH/128=2, B=8)
// ---------------------------------------------------------------------------
__global__ __launch_bounds__(256, 2) void gemm_av_mma(
    const float* __restrict__ V, const u32* __restrict__ A,
    const float* __restrict__ gamma, float* __restrict__ out)
{
    const int nb = blockIdx.x * 128;
    const int cb = blockIdx.y * 128;
    const int b  = blockIdx.z;
    const int tid  = threadIdx.x;
    const int lane = tid & 31;
    const int w    = tid >> 5;
    const int gid  = lane >> 2;
    const int ctid = lane & 3;
    const int n_base = (w & 1) * 64;
    const int c_base = (w >> 1) * 32;

    __shared__ u32 sv2[8 * 136];
    __shared__ u32 sa2[8 * 136];

    float acc[2][8][4];
#pragma unroll
    for (int i = 0; i < 2; i++)
#pragma unroll
        for (int j = 0; j < 8; j++)
#pragma unroll
            for (int l = 0; l < 4; l++) acc[i][j][l] = 0.f;

    const float* Vb = V + (size_t)b * CCH * MM;
    const u32* Ab = A + (size_t)b * NN * (MM / 2);

    const int row0 = tid >> 2, f0 = tid & 3;
    const int row1 = row0 + 64;

    float4 pv0, pv1, nv0, nv1;
    uint2 pa0, pa1, na0, na1;

#define AV_LOAD(v0, v1, a0v, a1v, M0)                                                           \
    {                                                                                           \
        v0  = *reinterpret_cast<const float4*>(&Vb[(size_t)(cb + row0) * MM + (M0) + f0 * 4]);   \
        v1  = *reinterpret_cast<const float4*>(&Vb[(size_t)(cb + row1) * MM + (M0) + f0 * 4]);   \
        a0v = *reinterpret_cast<const uint2*>(&Ab[(size_t)(nb + row0) * (MM / 2) + ((M0) >> 1) + f0 * 2]); \
        a1v = *reinterpret_cast<const uint2*>(&Ab[(size_t)(nb + row1) * (MM / 2) + ((M0) >> 1) + f0 * 2]); \
    }

    AV_LOAD(pv0, pv1, pa0, pa1, 0);

    for (int m0 = 0; m0 < MM; m0 += 16) {
        sv2[(f0 * 2) * 136 + row0]     = pkbf(pv0.x, pv0.y);
        sv2[(f0 * 2 + 1) * 136 + row0] = pkbf(pv0.z, pv0.w);
        sv2[(f0 * 2) * 136 + row1]     = pkbf(pv1.x, pv1.y);
        sv2[(f0 * 2 + 1) * 136 + row1] = pkbf(pv1.z, pv1.w);
        sa2[(f0 * 2) * 136 + row0]     = pa0.x;
        sa2[(f0 * 2 + 1) * 136 + row0] = pa0.y;
        sa2[(f0 * 2) * 136 + row1]     = pa1.x;
        sa2[(f0 * 2 + 1) * 136 + row1] = pa1.y;
        __syncthreads();

        if (m0 + 16 < MM) AV_LOAD(nv0, nv1, na0, na1, m0 + 16);

        u32 a[2][4];
#pragma unroll
        for (int rm = 0; rm < 2; rm++) {
            int c0 = c_base + rm * 16;
            a[rm][0] = sv2[ctid * 136 + c0 + gid];
            a[rm][1] = sv2[ctid * 136 + c0 + gid + 8];
            a[rm][2] = sv2[(ctid + 4) * 136 + c0 + gid];
            a[rm][3] = sv2[(ctid + 4) * 136 + c0 + gid + 8];
        }
#pragma unroll
        for (int f = 0; f < 8; f++) {
            u32 bf[2];
            bf[0] = sa2[ctid * 136 + n_base + f * 8 + gid];
            bf[1] = sa2[(ctid + 4) * 136 + n_base + f * 8 + gid];
            mma_bf16(acc[0][f], a[0], bf);
            mma_bf16(acc[1][f], a[1], bf);
        }
        __syncthreads();

        pv0 = nv0; pv1 = nv1; pa0 = na0; pa1 = na1;
    }

    const float gm = gamma[0];
#pragma unroll
    for (int rm = 0; rm < 2; rm++) {
#pragma unroll
        for (int f = 0; f < 8; f++) {
            int c0 = cb + c_base + rm * 16 + gid;
            int nn2 = nb + n_base + f * 8 + 2 * ctid;
            float2 s0 = {gm * acc[rm][f][0], gm * acc[rm][f][1]};
            float2 s1 = {gm * acc[rm][f][2], gm * acc[rm][f][3]};
            *reinterpret_cast<float2*>(&out[((size_t)b * CCH + c0) * NN + nn2])     = s0;
            *reinterpret_cast<float2*>(&out[((size_t)b * CCH + c0 + 8) * NN + nn2]) = s1;
        }
    }
}

// ---------------------------------------------------------------------------
extern "C" void kernel_launch(void* const* d_in, const int* in_sizes, int n_in,
                              void* d_out, int out_size)
{
    const float* x        = (const float*)d_in[0];
    const float* y        = (const float*)d_in[1];
    const float* Wq       = (const float*)d_in[2];
    const float* bq       = (const float*)d_in[3];
    const float* gq_scale = (const float*)d_in[4];
    const float* gq_bias  = (const float*)d_in[5];
    const float* Wk       = (const float*)d_in[6];
    const float* bk       = (const float*)d_in[7];
    const float* gk_scale = (const float*)d_in[8];
    const float* gk_bias  = (const float*)d_in[9];
    const float* Wv       = (const float*)d_in[10];
    const float* bv       = (const float*)d_in[11];
    const float* gv_scale = (const float*)d_in[12];
    const float* gv_bias  = (const float*)d_in[13];
    const float* gamma    = (const float*)d_in[14];
    float* out = (float*)d_out;

    float *qp = nullptr, *kp = nullptr, *vp = nullptr, *ep = nullptr;
    u32 *ap = nullptr, *xpp = nullptr, *ypp = nullptr;
    u32 *wtp = nullptr, *wkp = nullptr, *wvp = nullptr;
    cudaGetSymbolAddress((void**)&qp, g_q);
    cudaGetSymbolAddress((void**)&kp, g_k);
    cudaGetSymbolAddress((void**)&vp, g_v);
    cudaGetSymbolAddress((void**)&ep, g_e);
    cudaGetSymbolAddress((void**)&ap, g_a);
    cudaGetSymbolAddress((void**)&xpp, g_xp);
    cudaGetSymbolAddress((void**)&ypp, g_yp);
    cudaGetSymbolAddress((void**)&wtp, g_wt3);
    cudaGetSymbolAddress((void**)&wkp, g_wk3);
    cudaGetSymbolAddress((void**)&wvp, g_wv3);

    xpack_kernel<<<(BATCH * 128 * NN + 255) / 256, 256>>>(x, xpp);
    xpack_kernel<<<(BATCH * 128 * NN + 255) / 256, 256>>>(y, ypp);
    transpose_w3<<<(9 * 128 * 256 + 255) / 256, 256>>>(Wq, wtp);
    transpose_w2<<<(4 * 128 * 256 + 255) / 256, 256>>>(Wk, Wv, wkp, wvp);

    conv3_mma<<<dim3(HH / 2, CCH / 64, BATCH), 256>>>(wtp, xpp, bq, qp);
    conv2kv_mma<<<dim3(HK / 4, CCH / 64, BATCH), 256>>>(wkp, wvp, ypp, bk, bv, kp, vp);

    gn_silu_kernel<<<BATCH * 32, 512>>>(qp, gq_scale, gq_bias, NN);
    gn_silu_kernel<<<BATCH * 32, 512>>>(kp, gk_scale, gk_bias, MM);
    gn_silu_kernel<<<BATCH * 32, 512>>>(vp, gv_scale, gv_bias, MM);

    gemm_qk_mma<<<dim3(MM / 128, NN / 128, BATCH), 256>>>(qp, kp, ep);
    softmax_kernel<<<BATCH * NN / 8, 256>>>(ep, ap);
    gemm_av_mma<<<dim3(NN / 128, CCH / 128, BATCH), 256>>>(vp, ap, gamma, out);
}

// round 14
// speedup vs baseline: 1.3678x; 1.3678x over previous
#include <cuda_runtime.h>
#include <math.h>

#define BATCH 8
#define CCH   256
#define HH    64
#define WW    64
#define NN    4096   // HH*WW
#define MM    1024   // (HH/2)*(WW/2)
#define HK    32
#define WK    32

typedef unsigned long long u64;
typedef unsigned int u32;

__device__ __forceinline__ u32 f2tf(float f) {
    u32 u; asm("cvt.rna.tf32.f32 %0,%1;" : "=r"(u) : "f"(f)); return u;
}
// pack (lo, hi) floats -> bf16x2 word (lo in low half)
__device__ __forceinline__ u32 pkbf(float lo, float hi) {
    u32 d; asm("cvt.rn.bf16x2.f32 %0,%1,%2;" : "=r"(d) : "f"(hi), "f"(lo)); return d;
}
__device__ __forceinline__ void mma_tf32(float* d, const u32* a, const u32* b) {
    asm volatile(
        "mma.sync.aligned.m16n8k8.row.col.f32.tf32.tf32.f32 "
        "{%0,%1,%2,%3},{%4,%5,%6,%7},{%8,%9},{%0,%1,%2,%3};"
        : "+f"(d[0]), "+f"(d[1]), "+f"(d[2]), "+f"(d[3])
        : "r"(a[0]), "r"(a[1]), "r"(a[2]), "r"(a[3]), "r"(b[0]), "r"(b[1]));
}
__device__ __forceinline__ void mma_bf16(float* d, const u32* a, const u32* b) {
    asm volatile(
        "mma.sync.aligned.m16n8k16.row.col.f32.bf16.bf16.f32 "
        "{%0,%1,%2,%3},{%4,%5,%6,%7},{%8,%9},{%0,%1,%2,%3};"
        : "+f"(d[0]), "+f"(d[1]), "+f"(d[2]), "+f"(d[3])
        : "r"(a[0]), "r"(a[1]), "r"(a[2]), "r"(a[3]), "r"(b[0]), "r"(b[1]));
}

// Scratch
__device__ float g_q[(size_t)BATCH * CCH * NN];   // 32 MB
__device__ float g_k[(size_t)BATCH * CCH * MM];   // 8 MB
__device__ float g_v[(size_t)BATCH * CCH * MM];   // 8 MB
__device__ float g_e[(size_t)BATCH * NN * MM];    // 128 MB (pre-softmax, fp32)
__device__ u32   g_a[(size_t)BATCH * NN * (MM/2)]; // 64 MB (post-softmax, bf16x2)
__device__ u32   g_wt3[9 * 128 * 256];            // Wq [k][ci2][co] bf16x2
__device__ u32   g_wk2[4 * 256 * 256];            // Wk transposed, tf32
__device__ u32   g_wv2[4 * 256 * 256];            // Wv transposed, tf32

// ---------------------------------------------------------------------------
// Wq OIHW -> [k][ci2][co] packed bf16x2.
// ---------------------------------------------------------------------------
__global__ __launch_bounds__(256) void transpose_w3(
    const float* __restrict__ Wt, u32* __restrict__ wt3)
{
    int i = blockIdx.x * 256 + threadIdx.x;
    if (i < 9 * 128 * 256) {
        int co  = i & 255;
        int ci2 = (i >> 8) & 127;
        int k   = i >> 15;
        float lo = Wt[((size_t)co * 256 + 2 * ci2) * 9 + k];
        float hi = Wt[((size_t)co * 256 + 2 * ci2 + 1) * 9 + k];
        wt3[i] = pkbf(lo, hi);
    }
}

__global__ __launch_bounds__(256) void transpose_w2(
    const float* __restrict__ Wk, const float* __restrict__ Wv,
    u32* __restrict__ wk2, u32* __restrict__ wv2)
{
    int i = blockIdx.x * 256 + threadIdx.x;
    if (i < 4 * 256 * 256) {
        int co = i & 255;
        int ci = (i >> 8) & 255;
        int k  = i >> 16;
        wk2[i] = f2tf(Wk[((size_t)co * 256 + ci) * 4 + k]);
        wv2[i] = f2tf(Wv[((size_t)co * 256 + ci) * 4 + k]);
    }
}

// ---------------------------------------------------------------------------
// FUSED conv launch: interleaved block mapping over 1280 blocks.
//   bx % 5 == 4 -> conv2kv path (256 blocks)
//   else        -> conv3 path  (1024 blocks)
// Shared memory union: conv3 needs 7488 words, conv2kv 9856 words.
// ---------------------------------------------------------------------------
__global__ __launch_bounds__(256, 2) void conv_fused(
    const u32* __restrict__ wt3, const float* __restrict__ x,
    const float* __restrict__ bq, float* __restrict__ outQ,
    const u32* __restrict__ wtK, const u32* __restrict__ wtV,
    const float* __restrict__ y,
    const float* __restrict__ bK, const float* __restrict__ bV,
    float* __restrict__ outK, float* __restrict__ outV)
{
    __shared__ u32 smem_u[9856];   // 39.4 KB

    const int bx = blockIdx.x;
    const int tid  = threadIdx.x;
    const int lane = tid & 31;
    const int w    = tid >> 5;
    const int gid  = lane >> 2;
    const int ctid = lane & 3;
    const int co_base = (w >> 2) * 32;
    const int px_base = (w & 3) * 32;

    if (bx % 5 == 4) {
        // ================= conv2kv path (tf32, proven R10 version) =========
        const int c   = bx / 5;          // 0..255
        const int h0  = (c & 7) * 4;
        const int co0 = ((c >> 3) & 3) * 64;
        const int b   = c >> 5;

        u32* sy  = smem_u;               // 2*8*8*40 = 5120
        u32* swK = smem_u + 5120;        // 8*4*74 = 2368
        u32* swV = smem_u + 7488;        // 2368

        float accK[2][4][4], accV[2][4][4];
#pragma unroll
        for (int i = 0; i < 2; i++)
#pragma unroll
            for (int j = 0; j < 4; j++)
#pragma unroll
                for (int l = 0; l < 4; l++) { accK[i][j][l] = 0.f; accV[i][j][l] = 0.f; }

        const float* yb = y + (size_t)b * CCH * (HH * WW);
        const int ih0 = h0 * 2;

        float4 pin[4], pin2[4];

#define C2_LOAD(dst, CI0)                                                   \
        {                                                                   \
            _Pragma("unroll")                                               \
            for (int j = 0; j < 4; j++) {                                   \
                int i  = tid + j * 256;                                     \
                int r  = i >> 7;                                            \
                int ci = (i >> 4) & 7;                                      \
                int c4 = (i & 15) * 4;                                      \
                dst[j] = *reinterpret_cast<const float4*>(                  \
                    &yb[(size_t)((CI0) + ci) * (HH * WW) + (ih0 + r) * WW + c4]); \
            }                                                               \
        }

        C2_LOAD(pin, 0);

        for (int ci0 = 0; ci0 < CCH; ci0 += 8) {
#pragma unroll
            for (int j = 0; j < 4; j++) {
                int i  = tid + j * 256;
                int r  = i >> 7;
                int ci = (i >> 4) & 7;
                int c4 = (i & 15) * 4;
                float4 v = pin[j];
                u32* even = &sy[((0 * 8 + r) * 8 + ci) * 40 + (c4 >> 1)];
                u32* odd  = &sy[((8 + r) * 8 + ci) * 40 + (c4 >> 1)];
                even[0] = f2tf(v.x); odd[0] = f2tf(v.y);
                even[1] = f2tf(v.z); odd[1] = f2tf(v.w);
            }
            for (int i = tid; i < 8 * 4 * 16; i += 256) {
                int k   = i / 128;
                int ci  = (i >> 4) & 7;
                int co4 = (i & 15) * 4;
                size_t off = ((size_t)k * 256 + ci0 + ci) * 256 + co0 + co4;
                uint4 vk = *reinterpret_cast<const uint4*>(&wtK[off]);
                uint4 vv = *reinterpret_cast<const uint4*>(&wtV[off]);
                u32* dk = &swK[(ci * 4 + k) * 74 + co4];
                dk[0] = vk.x; dk[1] = vk.y; dk[2] = vk.z; dk[3] = vk.w;
                u32* dv = &swV[(ci * 4 + k) * 74 + co4];
                dv[0] = vv.x; dv[1] = vv.y; dv[2] = vv.z; dv[3] = vv.w;
            }
            __syncthreads();

            if (ci0 + 8 < CCH) C2_LOAD(pin2, ci0 + 8);

#pragma unroll
            for (int k = 0; k < 4; k++) {
                const int kh = k >> 1, kw = k & 1;
                u32 aK[2][4], aV[2][4];
#pragma unroll
                for (int rm = 0; rm < 2; rm++) {
                    int cof = co_base + rm * 16;
                    int r0 = (ctid * 4 + k) * 74 + cof;
                    int r1 = ((ctid + 4) * 4 + k) * 74 + cof;
                    aK[rm][0] = swK[r0 + gid];     aK[rm][1] = swK[r0 + gid + 8];
                    aK[rm][2] = swK[r1 + gid];     aK[rm][3] = swK[r1 + gid + 8];
                    aV[rm][0] = swV[r0 + gid];     aV[rm][1] = swV[r0 + gid + 8];
                    aV[rm][2] = swV[r1 + gid];     aV[rm][3] = swV[r1 + gid + 8];
                }
#pragma unroll
                for (int f = 0; f < 4; f++) {
                    int px = px_base + f * 8 + gid;
                    int r  = 2 * (px >> 5) + kh;
                    int wl = px & 31;
                    u32 bf[2];
                    bf[0] = sy[((kw * 8 + r) * 8 + ctid) * 40 + wl];
                    bf[1] = sy[((kw * 8 + r) * 8 + ctid + 4) * 40 + wl];
                    mma_tf32(accK[0][f], aK[0], bf);
                    mma_tf32(accK[1][f], aK[1], bf);
                    mma_tf32(accV[0][f], aV[0], bf);
                    mma_tf32(accV[1][f], aV[1], bf);
                }
            }
            __syncthreads();

#pragma unroll
            for (int j = 0; j < 4; j++) pin[j] = pin2[j];
        }

#pragma unroll
        for (int rm = 0; rm < 2; rm++) {
#pragma unroll
            for (int f = 0; f < 4; f++) {
                int coA = co0 + co_base + rm * 16 + gid;
                int coB = coA + 8;
                int px  = px_base + f * 8 + 2 * ctid;
                int n   = (h0 + (px >> 5)) * WK + (px & 31);
                size_t oA = ((size_t)b * CCH + coA) * MM + n;
                size_t oB = ((size_t)b * CCH + coB) * MM + n;
                float bkA = bK[coA], bkB = bK[coB];
                float bvA = bV[coA], bvB = bV[coB];
                float2 kA = {accK[rm][f][0] + bkA, accK[rm][f][1] + bkA};
                float2 kB = {accK[rm][f][2] + bkB, accK[rm][f][3] + bkB};
                float2 vA = {accV[rm][f][0] + bvA, accV[rm][f][1] + bvA};
                float2 vB = {accV[rm][f][2] + bvB, accV[rm][f][3] + bvB};
                *reinterpret_cast<float2*>(&outK[oA]) = kA;
                *reinterpret_cast<float2*>(&outK[oB]) = kB;
                *reinterpret_cast<float2*>(&outV[oA]) = vA;
                *reinterpret_cast<float2*>(&outV[oB]) = vB;
            }
        }
    } else {
        // ================= conv3 path (bf16, proven R10 version) ===========
        const int d   = (bx / 5) * 4 + (bx % 5);   // 0..1023
        const int h0  = (d & 31) * 2;
        const int co0 = ((d >> 5) & 3) * 64;
        const int b   = d >> 7;

        u32* sxt = smem_u;               // 4*8*72 = 2304
        u32* swt = smem_u + 2304;        // 8*9*72 = 5184

        float acc[2][4][4];
#pragma unroll
        for (int i = 0; i < 2; i++)
#pragma unroll
            for (int j = 0; j < 4; j++)
#pragma unroll
                for (int l = 0; l < 4; l++) acc[i][j][l] = 0.f;

        const float* xb = x + (size_t)b * CCH * (HH * WW);

        float plo[9], phi[9], plo2[9], phi2[9];

#define C3_LOAD(dlo, dhi, CI0)                                              \
        {                                                                   \
            _Pragma("unroll")                                               \
            for (int j = 0; j < 9; j++) {                                   \
                int i = tid + j * 256;                                      \
                if (i < 2112) {                                             \
                    int r   = i / 528;                                      \
                    int c2  = (i / 66) & 7;                                 \
                    int col = i % 66;                                       \
                    int gh = h0 - 1 + r;                                    \
                    int gw = col - 1;                                       \
                    float vlo = 0.f, vhi = 0.f;                             \
                    if ((unsigned)gh < HH && (unsigned)gw < WW) {           \
                        size_t base = (size_t)((CI0) + 2 * c2) * (HH * WW)  \
                                      + gh * WW + gw;                       \
                        vlo = xb[base];                                     \
                        vhi = xb[base + HH * WW];                           \
                    }                                                       \
                    dlo[j] = vlo; dhi[j] = vhi;                             \
                }                                                           \
            }                                                               \
        }

        C3_LOAD(plo, phi, 0);

        for (int ci0 = 0; ci0 < CCH; ci0 += 16) {
#pragma unroll
            for (int j = 0; j < 9; j++) {
                int i = tid + j * 256;
                if (i < 2112) {
                    int r   = i / 528;
                    int c2  = (i / 66) & 7;
                    int col = i % 66;
                    sxt[(r * 8 + c2) * 72 + col] = pkbf(plo[j], phi[j]);
                }
            }
            for (int i = tid; i < 8 * 9 * 16; i += 256) {
                int k   = i / 128;
                int c2  = (i >> 4) & 7;
                int co4 = (i & 15) * 4;
                uint4 v = *reinterpret_cast<const uint4*>(
                    &wt3[((size_t)k * 128 + (ci0 >> 1) + c2) * 256 + co0 + co4]);
                *reinterpret_cast<uint4*>(&swt[(c2 * 9 + k) * 72 + co4]) = v;
            }
            __syncthreads();

            if (ci0 + 16 < CCH) C3_LOAD(plo2, phi2, ci0 + 16);

#pragma unroll
            for (int k = 0; k < 9; k++) {
                const int kh = k / 3, kw = k % 3;
                u32 a[2][4];
#pragma unroll
                for (int rm = 0; rm < 2; rm++) {
                    int cof = co_base + rm * 16;
                    a[rm][0] = swt[((ctid) * 9 + k) * 72 + cof + gid];
                    a[rm][1] = swt[((ctid) * 9 + k) * 72 + cof + gid + 8];
                    a[rm][2] = swt[((ctid + 4) * 9 + k) * 72 + cof + gid];
                    a[rm][3] = swt[((ctid + 4) * 9 + k) * 72 + cof + gid + 8];
                }
#pragma unroll
                for (int f = 0; f < 4; f++) {
                    int px = px_base + f * 8 + gid;
                    int rl = px >> 6;
                    int wc = (px & 63) + kw;
                    u32 bf[2];
                    bf[0] = sxt[((rl + kh) * 8 + ctid) * 72 + wc];
                    bf[1] = sxt[((rl + kh) * 8 + ctid + 4) * 72 + wc];
                    mma_bf16(acc[0][f], a[0], bf);
                    mma_bf16(acc[1][f], a[1], bf);
                }
            }
            __syncthreads();

#pragma unroll
            for (int j = 0; j < 9; j++) { plo[j] = plo2[j]; phi[j] = phi2[j]; }
        }

#pragma unroll
        for (int rm = 0; rm < 2; rm++) {
#pragma unroll
            for (int f = 0; f < 4; f++) {
                int coA = co0 + co_base + rm * 16 + gid;
                int coB = coA + 8;
                int px  = px_base + f * 8 + 2 * ctid;
                int n   = (h0 + (px >> 6)) * WW + (px & 63);
                float bA = bq[coA], bB = bq[coB];
                float2 sA = {acc[rm][f][0] + bA, acc[rm][f][1] + bA};
                float2 sB = {acc[rm][f][2] + bB, acc[rm][f][3] + bB};
                *reinterpret_cast<float2*>(&outQ[((size_t)b * CCH + coA) * NN + n]) = sA;
                *reinterpret_cast<float2*>(&outQ[((size_t)b * CCH + coB) * NN + n]) = sB;
            }
        }
    }
}

// ---------------------------------------------------------------------------
// GroupNorm(32 groups of 8 ch) + affine + SiLU, in place. float4, 512 thr.
// ---------------------------------------------------------------------------
__global__ __launch_bounds__(512) void gn_silu_kernel(
    float* __restrict__ buf, const float* __restrict__ scale,
    const float* __restrict__ bias, int S)
{
    const int b = blockIdx.x >> 5;
    const int g = blockIdx.x & 31;
    float* base = buf + ((size_t)b * CCH + g * 8) * S;
    float4* p4 = reinterpret_cast<float4*>(base);
    const int tot4 = (8 * S) >> 2;
    const int tid = threadIdx.x;

    float s = 0.f, ss = 0.f;
    for (int i = tid; i < tot4; i += 512) {
        float4 v = p4[i];
        s += v.x + v.y + v.z + v.w;
        ss = fmaf(v.x, v.x, ss);
        ss = fmaf(v.y, v.y, ss);
        ss = fmaf(v.z, v.z, ss);
        ss = fmaf(v.w, v.w, ss);
    }
    __shared__ float r1[512], r2[512];
    r1[tid] = s; r2[tid] = ss;
    __syncthreads();
    for (int st = 256; st > 0; st >>= 1) {
        if (tid < st) { r1[tid] += r1[tid + st]; r2[tid] += r2[tid + st]; }
        __syncthreads();
    }
    const float tot = (float)(8 * S);
    const float mu   = r1[0] / tot;
    const float var  = r2[0] / tot - mu * mu;
    const float rstd = rsqrtf(var + 1e-5f);

    const int s4 = S >> 2;
    for (int i = tid; i < tot4; i += 512) {
        int c = g * 8 + i / s4;
        float sc = scale[c] * rstd, bi = bias[c] - mu * scale[c] * rstd;
        float4 v = p4[i];
        v.x = fmaf(v.x, sc, bi);
        v.y = fmaf(v.y, sc, bi);
        v.z = fmaf(v.z, sc, bi);
        v.w = fmaf(v.w, sc, bi);
        v.x = v.x / (1.f + __expf(-v.x));
        v.y = v.y / (1.f + __expf(-v.y));
        v.z = v.z / (1.f + __expf(-v.z));
        v.w = v.w / (1.f + __expf(-v.w));
        p4[i] = v;
    }
}

// ---------------------------------------------------------------------------
// E = (1/16) Q^T K  (bf16 m16n8k16), staged loads double-buffered.
// grid: (MM/128=8, NN/128=32, B=8)
// ---------------------------------------------------------------------------
__global__ __launch_bounds__(256, 2) void gemm_qk_mma(
    const float* __restrict__ Q, const float* __restrict__ K,
    float* __restrict__ E)
{
    const int mb = blockIdx.x * 128;
    const int nb = blockIdx.y * 128;
    const int b  = blockIdx.z;
    const int tid  = threadIdx.x;
    const int lane = tid & 31;
    const int w    = tid >> 5;
    const int gid  = lane >> 2;
    const int ctid = lane & 3;
    const int m_base = (w & 1) * 64;
    const int n_base = (w >> 1) * 32;

    __shared__ u32 sq2[8 * 136];
    __shared__ u32 sk2[8 * 136];

    float acc[2][8][4];
#pragma unroll
    for (int i = 0; i < 2; i++)
#pragma unroll
        for (int j = 0; j < 8; j++)
#pragma unroll
            for (int l = 0; l < 4; l++) acc[i][j][l] = 0.f;

    const float* Qb = Q + (size_t)b * CCH * NN + nb;
    const float* Kb = K + (size_t)b * CCH * MM + mb;

    const int kc  = tid >> 5;
    const int col = (lane) * 4;

    float4 pq0, pq1, pk0, pk1, nq0, nq1, nk0, nk1;

#define QK_LOAD(q0, q1, k0, k1, C0)                                                        \
    {                                                                                      \
        q0 = *reinterpret_cast<const float4*>(&Qb[(size_t)((C0) + 2 * kc) * NN + col]);     \
        q1 = *reinterpret_cast<const float4*>(&Qb[(size_t)((C0) + 2 * kc + 1) * NN + col]); \
        k0 = *reinterpret_cast<const float4*>(&Kb[(size_t)((C0) + 2 * kc) * MM + col]);     \
        k1 = *reinterpret_cast<const float4*>(&Kb[(size_t)((C0) + 2 * kc + 1) * MM + col]); \
    }

    QK_LOAD(pq0, pq1, pk0, pk1, 0);

    for (int c0 = 0; c0 < CCH; c0 += 16) {
        uint4 qs = {pkbf(pq0.x, pq1.x), pkbf(pq0.y, pq1.y),
                    pkbf(pq0.z, pq1.z), pkbf(pq0.w, pq1.w)};
        uint4 ks = {pkbf(pk0.x, pk1.x), pkbf(pk0.y, pk1.y),
                    pkbf(pk0.z, pk1.z), pkbf(pk0.w, pk1.w)};
        *reinterpret_cast<uint4*>(&sq2[kc * 136 + col]) = qs;
        *reinterpret_cast<uint4*>(&sk2[kc * 136 + col]) = ks;
        __syncthreads();

        if (c0 + 16 < CCH) QK_LOAD(nq0, nq1, nk0, nk1, c0 + 16);

        u32 a[2][4];
#pragma unroll
        for (int rm = 0; rm < 2; rm++) {
            int n0 = n_base + rm * 16;
            a[rm][0] = sq2[ctid * 136 + n0 + gid];
            a[rm][1] = sq2[ctid * 136 + n0 + gid + 8];
            a[rm][2] = sq2[(ctid + 4) * 136 + n0 + gid];
            a[rm][3] = sq2[(ctid + 4) * 136 + n0 + gid + 8];
        }
#pragma unroll
        for (int f = 0; f < 8; f++) {
            u32 bf[2];
            bf[0] = sk2[ctid * 136 + m_base + f * 8 + gid];
            bf[1] = sk2[(ctid + 4) * 136 + m_base + f * 8 + gid];
            mma_bf16(acc[0][f], a[0], bf);
            mma_bf16(acc[1][f], a[1], bf);
        }
        __syncthreads();

        pq0 = nq0; pq1 = nq1; pk0 = nk0; pk1 = nk1;
    }

    const float scale = 0.0625f;
    float* Eb = E + ((size_t)b * NN + nb) * MM + mb;
#pragma unroll
    for (int rm = 0; rm < 2; rm++) {
#pragma unroll
        for (int f = 0; f < 8; f++) {
            int r0 = n_base + rm * 16 + gid;
            int cc = m_base + f * 8 + 2 * ctid;
            float2 s0 = {acc[rm][f][0] * scale, acc[rm][f][1] * scale};
            float2 s1 = {acc[rm][f][2] * scale, acc[rm][f][3] * scale};
            *reinterpret_cast<float2*>(&Eb[(size_t)r0 * MM + cc])       = s0;
            *reinterpret_cast<float2*>(&Eb[(size_t)(r0 + 8) * MM + cc]) = s1;
        }
    }
}

// ---------------------------------------------------------------------------
// Softmax over last dim (M=1024), fp32 in -> packed bf16x2 out (m-pairs).
// One WARP per row. grid: B*NN/8 = 4096.
// ---------------------------------------------------------------------------
__global__ __launch_bounds__(256) void softmax_kernel(
    const float* __restrict__ E, u32* __restrict__ A)
{
    const int warp = threadIdx.x >> 5;
    const int lane = threadIdx.x & 31;
    const size_t row = (size_t)blockIdx.x * 8 + warp;
    const float4* p = reinterpret_cast<const float4*>(E + row * MM);
    u32* pa = A + row * (MM / 2);

    float4 v[8];
    float mx = -1e30f;
#pragma unroll
    for (int i = 0; i < 8; i++) {
        v[i] = p[lane + 32 * i];
        mx = fmaxf(mx, fmaxf(fmaxf(v[i].x, v[i].y), fmaxf(v[i].z, v[i].w)));
    }
#pragma unroll
    for (int o = 16; o > 0; o >>= 1)
        mx = fmaxf(mx, __shfl_xor_sync(0xFFFFFFFFu, mx, o));

    float sum = 0.f;
#pragma unroll
    for (int i = 0; i < 8; i++) {
        v[i].x = __expf(v[i].x - mx);
        v[i].y = __expf(v[i].y - mx);
        v[i].z = __expf(v[i].z - mx);
        v[i].w = __expf(v[i].w - mx);
        sum += v[i].x + v[i].y + v[i].z + v[i].w;
    }
#pragma unroll
    for (int o = 16; o > 0; o >>= 1)
        sum += __shfl_xor_sync(0xFFFFFFFFu, sum, o);

    float inv = 1.f / sum;
#pragma unroll
    for (int i = 0; i < 8; i++) {
        uint2 st;
        st.x = pkbf(v[i].x * inv, v[i].y * inv);
        st.y = pkbf(v[i].z * inv, v[i].w * inv);
        *reinterpret_cast<uint2*>(&pa[2 * (lane + 32 * i)]) = st;
    }
}

// ---------------------------------------------------------------------------
// out = gamma * V A^T (bf16 m16n8k16). A read pre-packed bf16x2 (m-pairs).
// grid: (NN/128=32, CCH/128=2, B=8)
// ---------------------------------------------------------------------------
__global__ __launch_bounds__(256, 2) void gemm_av_mma(
    const float* __restrict__ V, const u32* __restrict__ A,
    const float* __restrict__ gamma, float* __restrict__ out)
{
    const int nb = blockIdx.x * 128;
    const int cb = blockIdx.y * 128;
    const int b  = blockIdx.z;
    const int tid  = threadIdx.x;
    const int lane = tid & 31;
    const int w    = tid >> 5;
    const int gid  = lane >> 2;
    const int ctid = lane & 3;
    const int n_base = (w & 1) * 64;
    const int c_base = (w >> 1) * 32;

    __shared__ u32 sv2[8 * 136];
    __shared__ u32 sa2[8 * 136];

    float acc[2][8][4];
#pragma unroll
    for (int i = 0; i < 2; i++)
#pragma unroll
        for (int j = 0; j < 8; j++)
#pragma unroll
            for (int l = 0; l < 4; l++) acc[i][j][l] = 0.f;

    const float* Vb = V + (size_t)b * CCH * MM;
    const u32* Ab = A + (size_t)b * NN * (MM / 2);

    const int row0 = tid >> 2, f0 = tid & 3;
    const int row1 = row0 + 64;

    float4 pv0, pv1, nv0, nv1;
    uint2 pa0, pa1, na0, na1;

#define AV_LOAD(v0, v1, a0v, a1v, M0)                                                           \
    {                                                                                           \
        v0  = *reinterpret_cast<const float4*>(&Vb[(size_t)(cb + row0) * MM + (M0) + f0 * 4]);   \
        v1  = *reinterpret_cast<const float4*>(&Vb[(size_t)(cb + row1) * MM + (M0) + f0 * 4]);   \
        a0v = *reinterpret_cast<const uint2*>(&Ab[(size_t)(nb + row0) * (MM / 2) + ((M0) >> 1) + f0 * 2]); \
        a1v = *reinterpret_cast<const uint2*>(&Ab[(size_t)(nb + row1) * (MM / 2) + ((M0) >> 1) + f0 * 2]); \
    }

    AV_LOAD(pv0, pv1, pa0, pa1, 0);

    for (int m0 = 0; m0 < MM; m0 += 16) {
        sv2[(f0 * 2) * 136 + row0]     = pkbf(pv0.x, pv0.y);
        sv2[(f0 * 2 + 1) * 136 + row0] = pkbf(pv0.z, pv0.w);
        sv2[(f0 * 2) * 136 + row1]     = pkbf(pv1.x, pv1.y);
        sv2[(f0 * 2 + 1) * 136 + row1] = pkbf(pv1.z, pv1.w);
        sa2[(f0 * 2) * 136 + row0]     = pa0.x;
        sa2[(f0 * 2 + 1) * 136 + row0] = pa0.y;
        sa2[(f0 * 2) * 136 + row1]     = pa1.x;
        sa2[(f0 * 2 + 1) * 136 + row1] = pa1.y;
        __syncthreads();

        if (m0 + 16 < MM) AV_LOAD(nv0, nv1, na0, na1, m0 + 16);

        u32 a[2][4];
#pragma unroll
        for (int rm = 0; rm < 2; rm++) {
            int c0 = c_base + rm * 16;
            a[rm][0] = sv2[ctid * 136 + c0 + gid];
            a[rm][1] = sv2[ctid * 136 + c0 + gid + 8];
            a[rm][2] = sv2[(ctid + 4) * 136 + c0 + gid];
            a[rm][3] = sv2[(ctid + 4) * 136 + c0 + gid + 8];
        }
#pragma unroll
        for (int f = 0; f < 8; f++) {
            u32 bf[2];
            bf[0] = sa2[ctid * 136 + n_base + f * 8 + gid];
            bf[1] = sa2[(ctid + 4) * 136 + n_base + f * 8 + gid];
            mma_bf16(acc[0][f], a[0], bf);
            mma_bf16(acc[1][f], a[1], bf);
        }
        __syncthreads();

        pv0 = nv0; pv1 = nv1; pa0 = na0; pa1 = na1;
    }

    const float gm = gamma[0];
#pragma unroll
    for (int rm = 0; rm < 2; rm++) {
#pragma unroll
        for (int f = 0; f < 8; f++) {
            int c0 = cb + c_base + rm * 16 + gid;
            int nn2 = nb + n_base + f * 8 + 2 * ctid;
            float2 s0 = {gm * acc[rm][f][0], gm * acc[rm][f][1]};
            float2 s1 = {gm * acc[rm][f][2], gm * acc[rm][f][3]};
            *reinterpret_cast<float2*>(&out[((size_t)b * CCH + c0) * NN + nn2])     = s0;
            *reinterpret_cast<float2*>(&out[((size_t)b * CCH + c0 + 8) * NN + nn2]) = s1;
        }
    }
}

// ---------------------------------------------------------------------------
extern "C" void kernel_launch(void* const* d_in, const int* in_sizes, int n_in,
                              void* d_out, int out_size)
{
    const float* x        = (const float*)d_in[0];
    const float* y        = (const float*)d_in[1];
    const float* Wq       = (const float*)d_in[2];
    const float* bq       = (const float*)d_in[3];
    const float* gq_scale = (const float*)d_in[4];
    const float* gq_bias  = (const float*)d_in[5];
    const float* Wk       = (const float*)d_in[6];
    const float* bk       = (const float*)d_in[7];
    const float* gk_scale = (const float*)d_in[8];
    const float* gk_bias  = (const float*)d_in[9];
    const float* Wv       = (const float*)d_in[10];
    const float* bv       = (const float*)d_in[11];
    const float* gv_scale = (const float*)d_in[12];
    const float* gv_bias  = (const float*)d_in[13];
    const float* gamma    = (const float*)d_in[14];
    float* out = (float*)d_out;

    float *qp = nullptr, *kp = nullptr, *vp = nullptr, *ep = nullptr;
    u32 *ap = nullptr, *wtp = nullptr, *wkp = nullptr, *wvp = nullptr;
    cudaGetSymbolAddress((void**)&qp, g_q);
    cudaGetSymbolAddress((void**)&kp, g_k);
    cudaGetSymbolAddress((void**)&vp, g_v);
    cudaGetSymbolAddress((void**)&ep, g_e);
    cudaGetSymbolAddress((void**)&ap, g_a);
    cudaGetSymbolAddress((void**)&wtp, g_wt3);
    cudaGetSymbolAddress((void**)&wkp, g_wk2);
    cudaGetSymbolAddress((void**)&wvp, g_wv2);

    transpose_w3<<<(9 * 128 * 256 + 255) / 256, 256>>>(Wq, wtp);
    transpose_w2<<<(4 * 256 * 256 + 255) / 256, 256>>>(Wk, Wv, wkp, wvp);

    conv_fused<<<1280, 256>>>(wtp, x, bq, qp, wkp, wvp, y, bk, bv, kp, vp);

    gn_silu_kernel<<<BATCH * 32, 512>>>(qp, gq_scale, gq_bias, NN);
    gn_silu_kernel<<<BATCH * 32, 512>>>(kp, gk_scale, gk_bias, MM);
    gn_silu_kernel<<<BATCH * 32, 512>>>(vp, gv_scale, gv_bias, MM);

    gemm_qk_mma<<<dim3(MM / 128, NN / 128, BATCH), 256>>>(qp, kp, ep);
    softmax_kernel<<<BATCH * NN / 8, 256>>>(ep, ap);
    gemm_av_mma<<<dim3(NN / 128, CCH / 128, BATCH), 256>>>(vp, ap, gamma, out);
}

// round 15
// speedup vs baseline: 1.4052x; 1.0274x over previous
#include <cuda_runtime.h>
#include <math.h>

#define BATCH 8
#define CCH   256
#define HH    64
#define WW    64
#define NN    4096   // HH*WW
#define MM    1024   // (HH/2)*(WW/2)
#define HK    32
#define WK    32

typedef unsigned long long u64;
typedef unsigned int u32;

__device__ __forceinline__ u32 f2tf(float f) {
    u32 u; asm("cvt.rna.tf32.f32 %0,%1;" : "=r"(u) : "f"(f)); return u;
}
// pack (lo, hi) floats -> bf16x2 word (lo in low half)
__device__ __forceinline__ u32 pkbf(float lo, float hi) {
    u32 d; asm("cvt.rn.bf16x2.f32 %0,%1,%2;" : "=r"(d) : "f"(hi), "f"(lo)); return d;
}
__device__ __forceinline__ void mma_tf32(float* d, const u32* a, const u32* b) {
    asm volatile(
        "mma.sync.aligned.m16n8k8.row.col.f32.tf32.tf32.f32 "
        "{%0,%1,%2,%3},{%4,%5,%6,%7},{%8,%9},{%0,%1,%2,%3};"
        : "+f"(d[0]), "+f"(d[1]), "+f"(d[2]), "+f"(d[3])
        : "r"(a[0]), "r"(a[1]), "r"(a[2]), "r"(a[3]), "r"(b[0]), "r"(b[1]));
}
__device__ __forceinline__ void mma_bf16(float* d, const u32* a, const u32* b) {
    asm volatile(
        "mma.sync.aligned.m16n8k16.row.col.f32.bf16.bf16.f32 "
        "{%0,%1,%2,%3},{%4,%5,%6,%7},{%8,%9},{%0,%1,%2,%3};"
        : "+f"(d[0]), "+f"(d[1]), "+f"(d[2]), "+f"(d[3])
        : "r"(a[0]), "r"(a[1]), "r"(a[2]), "r"(a[3]), "r"(b[0]), "r"(b[1]));
}

// Scratch
__device__ float g_q[(size_t)BATCH * CCH * NN];   // 32 MB
__device__ float g_k[(size_t)BATCH * CCH * MM];   // 8 MB
__device__ float g_v[(size_t)BATCH * CCH * MM];   // 8 MB
__device__ float g_e[(size_t)BATCH * NN * MM];    // 128 MB (pre-softmax, fp32)
__device__ u32   g_a[(size_t)BATCH * NN * (MM/2)]; // 64 MB (post-softmax, bf16x2)
__device__ u32   g_wt3[9 * 128 * 256];            // Wq [k][ci2][co] bf16x2
__device__ u32   g_wk2[4 * 256 * 256];            // Wk transposed, tf32
__device__ u32   g_wv2[4 * 256 * 256];            // Wv transposed, tf32

// ---------------------------------------------------------------------------
__global__ __launch_bounds__(256) void transpose_w3(
    const float* __restrict__ Wt, u32* __restrict__ wt3)
{
    int i = blockIdx.x * 256 + threadIdx.x;
    if (i < 9 * 128 * 256) {
        int co  = i & 255;
        int ci2 = (i >> 8) & 127;
        int k   = i >> 15;
        float lo = Wt[((size_t)co * 256 + 2 * ci2) * 9 + k];
        float hi = Wt[((size_t)co * 256 + 2 * ci2 + 1) * 9 + k];
        wt3[i] = pkbf(lo, hi);
    }
}

__global__ __launch_bounds__(256) void transpose_w2(
    const float* __restrict__ Wk, const float* __restrict__ Wv,
    u32* __restrict__ wk2, u32* __restrict__ wv2)
{
    int i = blockIdx.x * 256 + threadIdx.x;
    if (i < 4 * 256 * 256) {
        int co = i & 255;
        int ci = (i >> 8) & 255;
        int k  = i >> 16;
        wk2[i] = f2tf(Wk[((size_t)co * 256 + ci) * 4 + k]);
        wv2[i] = f2tf(Wv[((size_t)co * 256 + ci) * 4 + k]);
    }
}

// ---------------------------------------------------------------------------
// FUSED conv launch, LJF mapping over 1280 blocks:
//   bx < 256  -> conv2kv path (long CTAs, start in wave 1)
//   bx >= 256 -> conv3 path (1024 blocks, backfill)
// ---------------------------------------------------------------------------
__global__ __launch_bounds__(256, 2) void conv_fused(
    const u32* __restrict__ wt3, const float* __restrict__ x,
    const float* __restrict__ bq, float* __restrict__ outQ,
    const u32* __restrict__ wtK, const u32* __restrict__ wtV,
    const float* __restrict__ y,
    const float* __restrict__ bK, const float* __restrict__ bV,
    float* __restrict__ outK, float* __restrict__ outV)
{
    __shared__ u32 smem_u[9856];   // 39.4 KB union

    const int bx = blockIdx.x;
    const int tid  = threadIdx.x;
    const int lane = tid & 31;
    const int w    = tid >> 5;
    const int gid  = lane >> 2;
    const int ctid = lane & 3;
    const int co_base = (w >> 2) * 32;
    const int px_base = (w & 3) * 32;

    if (bx < 256) {
        // ================= conv2kv path (tf32) =============================
        const int c   = bx;              // 0..255
        const int h0  = (c & 7) * 4;
        const int co0 = ((c >> 3) & 3) * 64;
        const int b   = c >> 5;

        u32* sy  = smem_u;               // 5120
        u32* swK = smem_u + 5120;        // 2368
        u32* swV = smem_u + 7488;        // 2368

        float accK[2][4][4], accV[2][4][4];
#pragma unroll
        for (int i = 0; i < 2; i++)
#pragma unroll
            for (int j = 0; j < 4; j++)
#pragma unroll
                for (int l = 0; l < 4; l++) { accK[i][j][l] = 0.f; accV[i][j][l] = 0.f; }

        const float* yb = y + (size_t)b * CCH * (HH * WW);
        const int ih0 = h0 * 2;

        float4 pin[4], pin2[4];

#define C2_LOAD(dst, CI0)                                                   \
        {                                                                   \
            _Pragma("unroll")                                               \
            for (int j = 0; j < 4; j++) {                                   \
                int i  = tid + j * 256;                                     \
                int r  = i >> 7;                                            \
                int ci = (i >> 4) & 7;                                      \
                int c4 = (i & 15) * 4;                                      \
                dst[j] = *reinterpret_cast<const float4*>(                  \
                    &yb[(size_t)((CI0) + ci) * (HH * WW) + (ih0 + r) * WW + c4]); \
            }                                                               \
        }

        C2_LOAD(pin, 0);

        for (int ci0 = 0; ci0 < CCH; ci0 += 8) {
#pragma unroll
            for (int j = 0; j < 4; j++) {
                int i  = tid + j * 256;
                int r  = i >> 7;
                int ci = (i >> 4) & 7;
                int c4 = (i & 15) * 4;
                float4 v = pin[j];
                u32* even = &sy[((0 * 8 + r) * 8 + ci) * 40 + (c4 >> 1)];
                u32* odd  = &sy[((8 + r) * 8 + ci) * 40 + (c4 >> 1)];
                even[0] = f2tf(v.x); odd[0] = f2tf(v.y);
                even[1] = f2tf(v.z); odd[1] = f2tf(v.w);
            }
            for (int i = tid; i < 8 * 4 * 16; i += 256) {
                int k   = i / 128;
                int ci  = (i >> 4) & 7;
                int co4 = (i & 15) * 4;
                size_t off = ((size_t)k * 256 + ci0 + ci) * 256 + co0 + co4;
                uint4 vk = *reinterpret_cast<const uint4*>(&wtK[off]);
                uint4 vv = *reinterpret_cast<const uint4*>(&wtV[off]);
                u32* dk = &swK[(ci * 4 + k) * 74 + co4];
                dk[0] = vk.x; dk[1] = vk.y; dk[2] = vk.z; dk[3] = vk.w;
                u32* dv = &swV[(ci * 4 + k) * 74 + co4];
                dv[0] = vv.x; dv[1] = vv.y; dv[2] = vv.z; dv[3] = vv.w;
            }
            __syncthreads();

            if (ci0 + 8 < CCH) C2_LOAD(pin2, ci0 + 8);

#pragma unroll
            for (int k = 0; k < 4; k++) {
                const int kh = k >> 1, kw = k & 1;
                u32 aK[2][4], aV[2][4];
#pragma unroll
                for (int rm = 0; rm < 2; rm++) {
                    int cof = co_base + rm * 16;
                    int r0 = (ctid * 4 + k) * 74 + cof;
                    int r1 = ((ctid + 4) * 4 + k) * 74 + cof;
                    aK[rm][0] = swK[r0 + gid];     aK[rm][1] = swK[r0 + gid + 8];
                    aK[rm][2] = swK[r1 + gid];     aK[rm][3] = swK[r1 + gid + 8];
                    aV[rm][0] = swV[r0 + gid];     aV[rm][1] = swV[r0 + gid + 8];
                    aV[rm][2] = swV[r1 + gid];     aV[rm][3] = swV[r1 + gid + 8];
                }
#pragma unroll
                for (int f = 0; f < 4; f++) {
                    int px = px_base + f * 8 + gid;
                    int r  = 2 * (px >> 5) + kh;
                    int wl = px & 31;
                    u32 bf[2];
                    bf[0] = sy[((kw * 8 + r) * 8 + ctid) * 40 + wl];
                    bf[1] = sy[((kw * 8 + r) * 8 + ctid + 4) * 40 + wl];
                    mma_tf32(accK[0][f], aK[0], bf);
                    mma_tf32(accK[1][f], aK[1], bf);
                    mma_tf32(accV[0][f], aV[0], bf);
                    mma_tf32(accV[1][f], aV[1], bf);
                }
            }
            __syncthreads();

#pragma unroll
            for (int j = 0; j < 4; j++) pin[j] = pin2[j];
        }

#pragma unroll
        for (int rm = 0; rm < 2; rm++) {
#pragma unroll
            for (int f = 0; f < 4; f++) {
                int coA = co0 + co_base + rm * 16 + gid;
                int coB = coA + 8;
                int px  = px_base + f * 8 + 2 * ctid;
                int n   = (h0 + (px >> 5)) * WK + (px & 31);
                size_t oA = ((size_t)b * CCH + coA) * MM + n;
                size_t oB = ((size_t)b * CCH + coB) * MM + n;
                float bkA = bK[coA], bkB = bK[coB];
                float bvA = bV[coA], bvB = bV[coB];
                float2 kA = {accK[rm][f][0] + bkA, accK[rm][f][1] + bkA};
                float2 kB = {accK[rm][f][2] + bkB, accK[rm][f][3] + bkB};
                float2 vA = {accV[rm][f][0] + bvA, accV[rm][f][1] + bvA};
                float2 vB = {accV[rm][f][2] + bvB, accV[rm][f][3] + bvB};
                *reinterpret_cast<float2*>(&outK[oA]) = kA;
                *reinterpret_cast<float2*>(&outK[oB]) = kB;
                *reinterpret_cast<float2*>(&outV[oA]) = vA;
                *reinterpret_cast<float2*>(&outV[oB]) = vB;
            }
        }
    } else {
        // ================= conv3 path (bf16) ===============================
        const int d   = bx - 256;        // 0..1023
        const int h0  = (d & 31) * 2;
        const int co0 = ((d >> 5) & 3) * 64;
        const int b   = d >> 7;

        u32* sxt = smem_u;               // 2304
        u32* swt = smem_u + 2304;        // 5184

        float acc[2][4][4];
#pragma unroll
        for (int i = 0; i < 2; i++)
#pragma unroll
            for (int j = 0; j < 4; j++)
#pragma unroll
                for (int l = 0; l < 4; l++) acc[i][j][l] = 0.f;

        const float* xb = x + (size_t)b * CCH * (HH * WW);

        float plo[9], phi[9], plo2[9], phi2[9];

#define C3_LOAD(dlo, dhi, CI0)                                              \
        {                                                                   \
            _Pragma("unroll")                                               \
            for (int j = 0; j < 9; j++) {                                   \
                int i = tid + j * 256;                                      \
                if (i < 2112) {                                             \
                    int r   = i / 528;                                      \
                    int c2  = (i / 66) & 7;                                 \
                    int col = i % 66;                                       \
                    int gh = h0 - 1 + r;                                    \
                    int gw = col - 1;                                       \
                    float vlo = 0.f, vhi = 0.f;                             \
                    if ((unsigned)gh < HH && (unsigned)gw < WW) {           \
                        size_t base = (size_t)((CI0) + 2 * c2) * (HH * WW)  \
                                      + gh * WW + gw;                       \
                        vlo = xb[base];                                     \
                        vhi = xb[base + HH * WW];                           \
                    }                                                       \
                    dlo[j] = vlo; dhi[j] = vhi;                             \
                }                                                           \
            }                                                               \
        }

        C3_LOAD(plo, phi, 0);

        for (int ci0 = 0; ci0 < CCH; ci0 += 16) {
#pragma unroll
            for (int j = 0; j < 9; j++) {
                int i = tid + j * 256;
                if (i < 2112) {
                    int r   = i / 528;
                    int c2  = (i / 66) & 7;
                    int col = i % 66;
                    sxt[(r * 8 + c2) * 72 + col] = pkbf(plo[j], phi[j]);
                }
            }
            for (int i = tid; i < 8 * 9 * 16; i += 256) {
                int k   = i / 128;
                int c2  = (i >> 4) & 7;
                int co4 = (i & 15) * 4;
                uint4 v = *reinterpret_cast<const uint4*>(
                    &wt3[((size_t)k * 128 + (ci0 >> 1) + c2) * 256 + co0 + co4]);
                *reinterpret_cast<uint4*>(&swt[(c2 * 9 + k) * 72 + co4]) = v;
            }
            __syncthreads();

            if (ci0 + 16 < CCH) C3_LOAD(plo2, phi2, ci0 + 16);

#pragma unroll
            for (int k = 0; k < 9; k++) {
                const int kh = k / 3, kw = k % 3;
                u32 a[2][4];
#pragma unroll
                for (int rm = 0; rm < 2; rm++) {
                    int cof = co_base + rm * 16;
                    a[rm][0] = swt[((ctid) * 9 + k) * 72 + cof + gid];
                    a[rm][1] = swt[((ctid) * 9 + k) * 72 + cof + gid + 8];
                    a[rm][2] = swt[((ctid + 4) * 9 + k) * 72 + cof + gid];
                    a[rm][3] = swt[((ctid + 4) * 9 + k) * 72 + cof + gid + 8];
                }
#pragma unroll
                for (int f = 0; f < 4; f++) {
                    int px = px_base + f * 8 + gid;
                    int rl = px >> 6;
                    int wc = (px & 63) + kw;
                    u32 bf[2];
                    bf[0] = sxt[((rl + kh) * 8 + ctid) * 72 + wc];
                    bf[1] = sxt[((rl + kh) * 8 + ctid + 4) * 72 + wc];
                    mma_bf16(acc[0][f], a[0], bf);
                    mma_bf16(acc[1][f], a[1], bf);
                }
            }
            __syncthreads();

#pragma unroll
            for (int j = 0; j < 9; j++) { plo[j] = plo2[j]; phi[j] = phi2[j]; }
        }

#pragma unroll
        for (int rm = 0; rm < 2; rm++) {
#pragma unroll
            for (int f = 0; f < 4; f++) {
                int coA = co0 + co_base + rm * 16 + gid;
                int coB = coA + 8;
                int px  = px_base + f * 8 + 2 * ctid;
                int n   = (h0 + (px >> 6)) * WW + (px & 63);
                float bA = bq[coA], bB = bq[coB];
                float2 sA = {acc[rm][f][0] + bA, acc[rm][f][1] + bA};
                float2 sB = {acc[rm][f][2] + bB, acc[rm][f][3] + bB};
                *reinterpret_cast<float2*>(&outQ[((size_t)b * CCH + coA) * NN + n]) = sA;
                *reinterpret_cast<float2*>(&outQ[((size_t)b * CCH + coB) * NN + n]) = sB;
            }
        }
    }
}

// ---------------------------------------------------------------------------
// GroupNorm(32 groups of 8 ch) + affine + SiLU, in place. float4, 512 thr.
// dual==1: blocks [0,256) -> buf0, [256,512) -> buf1 (both size S).
// ---------------------------------------------------------------------------
__global__ __launch_bounds__(512) void gn_silu_kernel(
    float* __restrict__ buf0, float* __restrict__ buf1,
    const float* __restrict__ scale0, const float* __restrict__ bias0,
    const float* __restrict__ scale1, const float* __restrict__ bias1,
    int S)
{
    int blk = blockIdx.x;
    float* buf = buf0;
    const float* scale = scale0;
    const float* bias  = bias0;
    if (buf1 != nullptr && blk >= 256) {
        blk -= 256; buf = buf1; scale = scale1; bias = bias1;
    }
    const int b = blk >> 5;
    const int g = blk & 31;
    float* base = buf + ((size_t)b * CCH + g * 8) * S;
    float4* p4 = reinterpret_cast<float4*>(base);
    const int tot4 = (8 * S) >> 2;
    const int tid = threadIdx.x;

    float s = 0.f, ss = 0.f;
    for (int i = tid; i < tot4; i += 512) {
        float4 v = p4[i];
        s += v.x + v.y + v.z + v.w;
        ss = fmaf(v.x, v.x, ss);
        ss = fmaf(v.y, v.y, ss);
        ss = fmaf(v.z, v.z, ss);
        ss = fmaf(v.w, v.w, ss);
    }
    __shared__ float r1[512], r2[512];
    r1[tid] = s; r2[tid] = ss;
    __syncthreads();
    for (int st = 256; st > 0; st >>= 1) {
        if (tid < st) { r1[tid] += r1[tid + st]; r2[tid] += r2[tid + st]; }
        __syncthreads();
    }
    const float tot = (float)(8 * S);
    const float mu   = r1[0] / tot;
    const float var  = r2[0] / tot - mu * mu;
    const float rstd = rsqrtf(var + 1e-5f);

    const int s4 = S >> 2;
    for (int i = tid; i < tot4; i += 512) {
        int c = g * 8 + i / s4;
        float sc = scale[c] * rstd, bi = bias[c] - mu * scale[c] * rstd;
        float4 v = p4[i];
        v.x = fmaf(v.x, sc, bi);
        v.y = fmaf(v.y, sc, bi);
        v.z = fmaf(v.z, sc, bi);
        v.w = fmaf(v.w, sc, bi);
        v.x = v.x / (1.f + __expf(-v.x));
        v.y = v.y / (1.f + __expf(-v.y));
        v.z = v.z / (1.f + __expf(-v.z));
        v.w = v.w / (1.f + __expf(-v.w));
        p4[i] = v;
    }
}

// ---------------------------------------------------------------------------
// E = (1/16) Q^T K  (bf16 m16n8k16), staged loads double-buffered.
// grid: (MM/128=8, NN/128=32, B=8)
// ---------------------------------------------------------------------------
__global__ __launch_bounds__(256, 2) void gemm_qk_mma(
    const float* __restrict__ Q, const float* __restrict__ K,
    float* __restrict__ E)
{
    const int mb = blockIdx.x * 128;
    const int nb = blockIdx.y * 128;
    const int b  = blockIdx.z;
    const int tid  = threadIdx.x;
    const int lane = tid & 31;
    const int w    = tid >> 5;
    const int gid  = lane >> 2;
    const int ctid = lane & 3;
    const int m_base = (w & 1) * 64;
    const int n_base = (w >> 1) * 32;

    __shared__ u32 sq2[8 * 136];
    __shared__ u32 sk2[8 * 136];

    float acc[2][8][4];
#pragma unroll
    for (int i = 0; i < 2; i++)
#pragma unroll
        for (int j = 0; j < 8; j++)
#pragma unroll
            for (int l = 0; l < 4; l++) acc[i][j][l] = 0.f;

    const float* Qb = Q + (size_t)b * CCH * NN + nb;
    const float* Kb = K + (size_t)b * CCH * MM + mb;

    const int kc  = tid >> 5;
    const int col = (lane) * 4;

    float4 pq0, pq1, pk0, pk1, nq0, nq1, nk0, nk1;

#define QK_LOAD(q0, q1, k0, k1, C0)                                                        \
    {                                                                                      \
        q0 = *reinterpret_cast<const float4*>(&Qb[(size_t)((C0) + 2 * kc) * NN + col]);     \
        q1 = *reinterpret_cast<const float4*>(&Qb[(size_t)((C0) + 2 * kc + 1) * NN + col]); \
        k0 = *reinterpret_cast<const float4*>(&Kb[(size_t)((C0) + 2 * kc) * MM + col]);     \
        k1 = *reinterpret_cast<const float4*>(&Kb[(size_t)((C0) + 2 * kc + 1) * MM + col]); \
    }

    QK_LOAD(pq0, pq1, pk0, pk1, 0);

    for (int c0 = 0; c0 < CCH; c0 += 16) {
        uint4 qs = {pkbf(pq0.x, pq1.x), pkbf(pq0.y, pq1.y),
                    pkbf(pq0.z, pq1.z), pkbf(pq0.w, pq1.w)};
        uint4 ks = {pkbf(pk0.x, pk1.x), pkbf(pk0.y, pk1.y),
                    pkbf(pk0.z, pk1.z), pkbf(pk0.w, pk1.w)};
        *reinterpret_cast<uint4*>(&sq2[kc * 136 + col]) = qs;
        *reinterpret_cast<uint4*>(&sk2[kc * 136 + col]) = ks;
        __syncthreads();

        if (c0 + 16 < CCH) QK_LOAD(nq0, nq1, nk0, nk1, c0 + 16);

        u32 a[2][4];
#pragma unroll
        for (int rm = 0; rm < 2; rm++) {
            int n0 = n_base + rm * 16;
            a[rm][0] = sq2[ctid * 136 + n0 + gid];
            a[rm][1] = sq2[ctid * 136 + n0 + gid + 8];
            a[rm][2] = sq2[(ctid + 4) * 136 + n0 + gid];
            a[rm][3] = sq2[(ctid + 4) * 136 + n0 + gid + 8];
        }
#pragma unroll
        for (int f = 0; f < 8; f++) {
            u32 bf[2];
            bf[0] = sk2[ctid * 136 + m_base + f * 8 + gid];
            bf[1] = sk2[(ctid + 4) * 136 + m_base + f * 8 + gid];
            mma_bf16(acc[0][f], a[0], bf);
            mma_bf16(acc[1][f], a[1], bf);
        }
        __syncthreads();

        pq0 = nq0; pq1 = nq1; pk0 = nk0; pk1 = nk1;
    }

    const float scale = 0.0625f;
    float* Eb = E + ((size_t)b * NN + nb) * MM + mb;
#pragma unroll
    for (int rm = 0; rm < 2; rm++) {
#pragma unroll
        for (int f = 0; f < 8; f++) {
            int r0 = n_base + rm * 16 + gid;
            int cc = m_base + f * 8 + 2 * ctid;
            float2 s0 = {acc[rm][f][0] * scale, acc[rm][f][1] * scale};
            float2 s1 = {acc[rm][f][2] * scale, acc[rm][f][3] * scale};
            *reinterpret_cast<float2*>(&Eb[(size_t)r0 * MM + cc])       = s0;
            *reinterpret_cast<float2*>(&Eb[(size_t)(r0 + 8) * MM + cc]) = s1;
        }
    }
}

// ---------------------------------------------------------------------------
// Softmax over last dim (M=1024), fp32 in -> packed bf16x2 out (m-pairs).
// One WARP per row. grid: B*NN/8 = 4096.
// ---------------------------------------------------------------------------
__global__ __launch_bounds__(256) void softmax_kernel(
    const float* __restrict__ E, u32* __restrict__ A)
{
    const int warp = threadIdx.x >> 5;
    const int lane = threadIdx.x & 31;
    const size_t row = (size_t)blockIdx.x * 8 + warp;
    const float4* p = reinterpret_cast<const float4*>(E + row * MM);
    u32* pa = A + row * (MM / 2);

    float4 v[8];
    float mx = -1e30f;
#pragma unroll
    for (int i = 0; i < 8; i++) {
        v[i] = p[lane + 32 * i];
        mx = fmaxf(mx, fmaxf(fmaxf(v[i].x, v[i].y), fmaxf(v[i].z, v[i].w)));
    }
#pragma unroll
    for (int o = 16; o > 0; o >>= 1)
        mx = fmaxf(mx, __shfl_xor_sync(0xFFFFFFFFu, mx, o));

    float sum = 0.f;
#pragma unroll
    for (int i = 0; i < 8; i++) {
        v[i].x = __expf(v[i].x - mx);
        v[i].y = __expf(v[i].y - mx);
        v[i].z = __expf(v[i].z - mx);
        v[i].w = __expf(v[i].w - mx);
        sum += v[i].x + v[i].y + v[i].z + v[i].w;
    }
#pragma unroll
    for (int o = 16; o > 0; o >>= 1)
        sum += __shfl_xor_sync(0xFFFFFFFFu, sum, o);

    float inv = 1.f / sum;
#pragma unroll
    for (int i = 0; i < 8; i++) {
        uint2 st;
        st.x = pkbf(v[i].x * inv, v[i].y * inv);
        st.y = pkbf(v[i].z * inv, v[i].w * inv);
        *reinterpret_cast<uint2*>(&pa[2 * (lane + 32 * i)]) = st;
    }
}

// ---------------------------------------------------------------------------
// out = gamma * V A^T (bf16 m16n8k16). A read pre-packed bf16x2 (m-pairs).
// grid: (NN/128=32, CCH/128=2, B=8)
// ---------------------------------------------------------------------------
__global__ __launch_bounds__(256, 2) void gemm_av_mma(
    const float* __restrict__ V, const u32* __restrict__ A,
    const float* __restrict__ gamma, float* __restrict__ out)
{
    const int nb = blockIdx.x * 128;
    const int cb = blockIdx.y * 128;
    const int b  = blockIdx.z;
    const int tid  = threadIdx.x;
    const int lane = tid & 31;
    const int w    = tid >> 5;
    const int gid  = lane >> 2;
    const int ctid = lane & 3;
    const int n_base = (w & 1) * 64;
    const int c_base = (w >> 1) * 32;

    __shared__ u32 sv2[8 * 136];
    __shared__ u32 sa2[8 * 136];

    float acc[2][8][4];
#pragma unroll
    for (int i = 0; i < 2; i++)
#pragma unroll
        for (int j = 0; j < 8; j++)
#pragma unroll
            for (int l = 0; l < 4; l++) acc[i][j][l] = 0.f;

    const float* Vb = V + (size_t)b * CCH * MM;
    const u32* Ab = A + (size_t)b * NN * (MM / 2);

    const int row0 = tid >> 2, f0 = tid & 3;
    const int row1 = row0 + 64;

    float4 pv0, pv1, nv0, nv1;
    uint2 pa0, pa1, na0, na1;

#define AV_LOAD(v0, v1, a0v, a1v, M0)                                                           \
    {                                                                                           \
        v0  = *reinterpret_cast<const float4*>(&Vb[(size_t)(cb + row0) * MM + (M0) + f0 * 4]);   \
        v1  = *reinterpret_cast<const float4*>(&Vb[(size_t)(cb + row1) * MM + (M0) + f0 * 4]);   \
        a0v = *reinterpret_cast<const uint2*>(&Ab[(size_t)(nb + row0) * (MM / 2) + ((M0) >> 1) + f0 * 2]); \
        a1v = *reinterpret_cast<const uint2*>(&Ab[(size_t)(nb + row1) * (MM / 2) + ((M0) >> 1) + f0 * 2]); \
    }

    AV_LOAD(pv0, pv1, pa0, pa1, 0);

    for (int m0 = 0; m0 < MM; m0 += 16) {
        sv2[(f0 * 2) * 136 + row0]     = pkbf(pv0.x, pv0.y);
        sv2[(f0 * 2 + 1) * 136 + row0] = pkbf(pv0.z, pv0.w);
        sv2[(f0 * 2) * 136 + row1]     = pkbf(pv1.x, pv1.y);
        sv2[(f0 * 2 + 1) * 136 + row1] = pkbf(pv1.z, pv1.w);
        sa2[(f0 * 2) * 136 + row0]     = pa0.x;
        sa2[(f0 * 2 + 1) * 136 + row0] = pa0.y;
        sa2[(f0 * 2) * 136 + row1]     = pa1.x;
        sa2[(f0 * 2 + 1) * 136 + row1] = pa1.y;
        __syncthreads();

        if (m0 + 16 < MM) AV_LOAD(nv0, nv1, na0, na1, m0 + 16);

        u32 a[2][4];
#pragma unroll
        for (int rm = 0; rm < 2; rm++) {
            int c0 = c_base + rm * 16;
            a[rm][0] = sv2[ctid * 136 + c0 + gid];
            a[rm][1] = sv2[ctid * 136 + c0 + gid + 8];
            a[rm][2] = sv2[(ctid + 4) * 136 + c0 + gid];
            a[rm][3] = sv2[(ctid + 4) * 136 + c0 + gid + 8];
        }
#pragma unroll
        for (int f = 0; f < 8; f++) {
            u32 bf[2];
            bf[0] = sa2[ctid * 136 + n_base + f * 8 + gid];
            bf[1] = sa2[(ctid + 4) * 136 + n_base + f * 8 + gid];
            mma_bf16(acc[0][f], a[0], bf);
            mma_bf16(acc[1][f], a[1], bf);
        }
        __syncthreads();

        pv0 = nv0; pv1 = nv1; pa0 = na0; pa1 = na1;
    }

    const float gm = gamma[0];
#pragma unroll
    for (int rm = 0; rm < 2; rm++) {
#pragma unroll
        for (int f = 0; f < 8; f++) {
            int c0 = cb + c_base + rm * 16 + gid;
            int nn2 = nb + n_base + f * 8 + 2 * ctid;
            float2 s0 = {gm * acc[rm][f][0], gm * acc[rm][f][1]};
            float2 s1 = {gm * acc[rm][f][2], gm * acc[rm][f][3]};
            *reinterpret_cast<float2*>(&out[((size_t)b * CCH + c0) * NN + nn2])     = s0;
            *reinterpret_cast<float2*>(&out[((size_t)b * CCH + c0 + 8) * NN + nn2]) = s1;
        }
    }
}

// ---------------------------------------------------------------------------
extern "C" void kernel_launch(void* const* d_in, const int* in_sizes, int n_in,
                              void* d_out, int out_size)
{
    const float* x        = (const float*)d_in[0];
    const float* y        = (const float*)d_in[1];
    const float* Wq       = (const float*)d_in[2];
    const float* bq       = (const float*)d_in[3];
    const float* gq_scale = (const float*)d_in[4];
    const float* gq_bias  = (const float*)d_in[5];
    const float* Wk       = (const float*)d_in[6];
    const float* bk       = (const float*)d_in[7];
    const float* gk_scale = (const float*)d_in[8];
    const float* gk_bias  = (const float*)d_in[9];
    const float* Wv       = (const float*)d_in[10];
    const float* bv       = (const float*)d_in[11];
    const float* gv_scale = (const float*)d_in[12];
    const float* gv_bias  = (const float*)d_in[13];
    const float* gamma    = (const float*)d_in[14];
    float* out = (float*)d_out;

    float *qp = nullptr, *kp = nullptr, *vp = nullptr, *ep = nullptr;
    u32 *ap = nullptr, *wtp = nullptr, *wkp = nullptr, *wvp = nullptr;
    cudaGetSymbolAddress((void**)&qp, g_q);
    cudaGetSymbolAddress((void**)&kp, g_k);
    cudaGetSymbolAddress((void**)&vp, g_v);
    cudaGetSymbolAddress((void**)&ep, g_e);
    cudaGetSymbolAddress((void**)&ap, g_a);
    cudaGetSymbolAddress((void**)&wtp, g_wt3);
    cudaGetSymbolAddress((void**)&wkp, g_wk2);
    cudaGetSymbolAddress((void**)&wvp, g_wv2);

    transpose_w3<<<(9 * 128 * 256 + 255) / 256, 256>>>(Wq, wtp);
    transpose_w2<<<(4 * 256 * 256 + 255) / 256, 256>>>(Wk, Wv, wkp, wvp);

    conv_fused<<<1280, 256>>>(wtp, x, bq, qp, wkp, wvp, y, bk, bv, kp, vp);

    // k and v GroupNorm merged into one launch; q separate (different S)
    gn_silu_kernel<<<BATCH * 64, 512>>>(kp, vp, gk_scale, gk_bias,
                                        gv_scale, gv_bias, MM);
    gn_silu_kernel<<<BATCH * 32, 512>>>(qp, nullptr, gq_scale, gq_bias,
                                        nullptr, nullptr, NN);

    gemm_qk_mma<<<dim3(MM / 128, NN / 128, BATCH), 256>>>(qp, kp, ep);
    softmax_kernel<<<BATCH * NN / 8, 256>>>(ep, ap);
    gemm_av_mma<<<dim3(NN / 128, CCH / 128, BATCH), 256>>>(vp, ap, gamma, out);
}

// round 16
// speedup vs baseline: 1.4608x; 1.0396x over previous
#include <cuda_runtime.h>
#include <math.h>

#define BATCH 8
#define CCH   256
#define HH    64
#define WW    64
#define NN    4096   // HH*WW
#define MM    1024   // (HH/2)*(WW/2)
#define HK    32
#define WK    32

typedef unsigned long long u64;
typedef unsigned int u32;

__device__ __forceinline__ u32 f2tf(float f) {
    u32 u; asm("cvt.rna.tf32.f32 %0,%1;" : "=r"(u) : "f"(f)); return u;
}
// pack (lo, hi) floats -> bf16x2 word (lo in low half)
__device__ __forceinline__ u32 pkbf(float lo, float hi) {
    u32 d; asm("cvt.rn.bf16x2.f32 %0,%1,%2;" : "=r"(d) : "f"(hi), "f"(lo)); return d;
}
__device__ __forceinline__ void mma_tf32(float* d, const u32* a, const u32* b) {
    asm volatile(
        "mma.sync.aligned.m16n8k8.row.col.f32.tf32.tf32.f32 "
        "{%0,%1,%2,%3},{%4,%5,%6,%7},{%8,%9},{%0,%1,%2,%3};"
        : "+f"(d[0]), "+f"(d[1]), "+f"(d[2]), "+f"(d[3])
        : "r"(a[0]), "r"(a[1]), "r"(a[2]), "r"(a[3]), "r"(b[0]), "r"(b[1]));
}
__device__ __forceinline__ void mma_bf16(float* d, const u32* a, const u32* b) {
    asm volatile(
        "mma.sync.aligned.m16n8k16.row.col.f32.bf16.bf16.f32 "
        "{%0,%1,%2,%3},{%4,%5,%6,%7},{%8,%9},{%0,%1,%2,%3};"
        : "+f"(d[0]), "+f"(d[1]), "+f"(d[2]), "+f"(d[3])
        : "r"(a[0]), "r"(a[1]), "r"(a[2]), "r"(a[3]), "r"(b[0]), "r"(b[1]));
}

// Scratch
__device__ float g_q[(size_t)BATCH * CCH * NN];   // 32 MB
__device__ float g_k[(size_t)BATCH * CCH * MM];   // 8 MB
__device__ float g_v[(size_t)BATCH * CCH * MM];   // 8 MB
__device__ float g_e[(size_t)BATCH * NN * MM];    // 128 MB (pre-softmax, fp32)
__device__ u32   g_a[(size_t)BATCH * NN * (MM/2)]; // 64 MB (post-softmax, bf16x2)
__device__ u32   g_xp[(size_t)BATCH * 128 * NN];  // 16 MB (x packed bf16x2)
__device__ u32   g_wt3[9 * 128 * 256];            // Wq [k][ci2][co] bf16x2
__device__ u32   g_wk2[4 * 256 * 256];            // Wk transposed, tf32
__device__ u32   g_wv2[4 * 256 * 256];            // Wv transposed, tf32

// ---------------------------------------------------------------------------
// Pack x: fp32 [b][ci][hw] -> bf16x2 [b][ci2][hw].
// ---------------------------------------------------------------------------
__global__ __launch_bounds__(256) void xpack_kernel(
    const float* __restrict__ x, u32* __restrict__ xp)
{
    size_t i = (size_t)blockIdx.x * 256 + threadIdx.x;
    if (i < (size_t)BATCH * 128 * NN) {
        int hw  = i & (NN - 1);
        int c2  = (i >> 12) & 127;
        int b   = i >> 19;
        size_t base = ((size_t)b * CCH + 2 * c2) * NN + hw;
        xp[i] = pkbf(x[base], x[base + NN]);
    }
}

__global__ __launch_bounds__(256) void transpose_w3(
    const float* __restrict__ Wt, u32* __restrict__ wt3)
{
    int i = blockIdx.x * 256 + threadIdx.x;
    if (i < 9 * 128 * 256) {
        int co  = i & 255;
        int ci2 = (i >> 8) & 127;
        int k   = i >> 15;
        float lo = Wt[((size_t)co * 256 + 2 * ci2) * 9 + k];
        float hi = Wt[((size_t)co * 256 + 2 * ci2 + 1) * 9 + k];
        wt3[i] = pkbf(lo, hi);
    }
}

__global__ __launch_bounds__(256) void transpose_w2(
    const float* __restrict__ Wk, const float* __restrict__ Wv,
    u32* __restrict__ wk2, u32* __restrict__ wv2)
{
    int i = blockIdx.x * 256 + threadIdx.x;
    if (i < 4 * 256 * 256) {
        int co = i & 255;
        int ci = (i >> 8) & 255;
        int k  = i >> 16;
        wk2[i] = f2tf(Wk[((size_t)co * 256 + ci) * 4 + k]);
        wv2[i] = f2tf(Wv[((size_t)co * 256 + ci) * 4 + k]);
    }
}

// ---------------------------------------------------------------------------
// FUSED conv launch, LJF mapping over 768 blocks:
//   bx < 256  -> conv2kv path (long CTAs, wave 1)
//   bx >= 256 -> conv3 path (512 blocks, 4 output rows each)
// ---------------------------------------------------------------------------
__global__ __launch_bounds__(256, 2) void conv_fused(
    const u32* __restrict__ wt3, const u32* __restrict__ xp,
    const float* __restrict__ bq, float* __restrict__ outQ,
    const u32* __restrict__ wtK, const u32* __restrict__ wtV,
    const float* __restrict__ y,
    const float* __restrict__ bK, const float* __restrict__ bV,
    float* __restrict__ outK, float* __restrict__ outV)
{
    __shared__ u32 smem_u[9856];   // union: conv2kv 9856, conv3 8640

    const int bx = blockIdx.x;
    const int tid  = threadIdx.x;
    const int lane = tid & 31;
    const int w    = tid >> 5;
    const int gid  = lane >> 2;
    const int ctid = lane & 3;
    const int co_base = (w >> 2) * 32;

    if (bx < 256) {
        // ================= conv2kv path (tf32, unchanged) ==================
        const int px_base = (w & 3) * 32;
        const int c   = bx;
        const int h0  = (c & 7) * 4;
        const int co0 = ((c >> 3) & 3) * 64;
        const int b   = c >> 5;

        u32* sy  = smem_u;
        u32* swK = smem_u + 5120;
        u32* swV = smem_u + 7488;

        float accK[2][4][4], accV[2][4][4];
#pragma unroll
        for (int i = 0; i < 2; i++)
#pragma unroll
            for (int j = 0; j < 4; j++)
#pragma unroll
                for (int l = 0; l < 4; l++) { accK[i][j][l] = 0.f; accV[i][j][l] = 0.f; }

        const float* yb = y + (size_t)b * CCH * (HH * WW);
        const int ih0 = h0 * 2;

        float4 pin[4], pin2[4];

#define C2_LOAD(dst, CI0)                                                   \
        {                                                                   \
            _Pragma("unroll")                                               \
            for (int j = 0; j < 4; j++) {                                   \
                int i  = tid + j * 256;                                     \
                int r  = i >> 7;                                            \
                int ci = (i >> 4) & 7;                                      \
                int c4 = (i & 15) * 4;                                      \
                dst[j] = *reinterpret_cast<const float4*>(                  \
                    &yb[(size_t)((CI0) + ci) * (HH * WW) + (ih0 + r) * WW + c4]); \
            }                                                               \
        }

        C2_LOAD(pin, 0);

        for (int ci0 = 0; ci0 < CCH; ci0 += 8) {
#pragma unroll
            for (int j = 0; j < 4; j++) {
                int i  = tid + j * 256;
                int r  = i >> 7;
                int ci = (i >> 4) & 7;
                int c4 = (i & 15) * 4;
                float4 v = pin[j];
                u32* even = &sy[((0 * 8 + r) * 8 + ci) * 40 + (c4 >> 1)];
                u32* odd  = &sy[((8 + r) * 8 + ci) * 40 + (c4 >> 1)];
                even[0] = f2tf(v.x); odd[0] = f2tf(v.y);
                even[1] = f2tf(v.z); odd[1] = f2tf(v.w);
            }
            for (int i = tid; i < 8 * 4 * 16; i += 256) {
                int k   = i / 128;
                int ci  = (i >> 4) & 7;
                int co4 = (i & 15) * 4;
                size_t off = ((size_t)k * 256 + ci0 + ci) * 256 + co0 + co4;
                uint4 vk = *reinterpret_cast<const uint4*>(&wtK[off]);
                uint4 vv = *reinterpret_cast<const uint4*>(&wtV[off]);
                u32* dk = &swK[(ci * 4 + k) * 74 + co4];
                dk[0] = vk.x; dk[1] = vk.y; dk[2] = vk.z; dk[3] = vk.w;
                u32* dv = &swV[(ci * 4 + k) * 74 + co4];
                dv[0] = vv.x; dv[1] = vv.y; dv[2] = vv.z; dv[3] = vv.w;
            }
            __syncthreads();

            if (ci0 + 8 < CCH) C2_LOAD(pin2, ci0 + 8);

#pragma unroll
            for (int k = 0; k < 4; k++) {
                const int kh = k >> 1, kw = k & 1;
                u32 aK[2][4], aV[2][4];
#pragma unroll
                for (int rm = 0; rm < 2; rm++) {
                    int cof = co_base + rm * 16;
                    int r0 = (ctid * 4 + k) * 74 + cof;
                    int r1 = ((ctid + 4) * 4 + k) * 74 + cof;
                    aK[rm][0] = swK[r0 + gid];     aK[rm][1] = swK[r0 + gid + 8];
                    aK[rm][2] = swK[r1 + gid];     aK[rm][3] = swK[r1 + gid + 8];
                    aV[rm][0] = swV[r0 + gid];     aV[rm][1] = swV[r0 + gid + 8];
                    aV[rm][2] = swV[r1 + gid];     aV[rm][3] = swV[r1 + gid + 8];
                }
#pragma unroll
                for (int f = 0; f < 4; f++) {
                    int px = px_base + f * 8 + gid;
                    int r  = 2 * (px >> 5) + kh;
                    int wl = px & 31;
                    u32 bf[2];
                    bf[0] = sy[((kw * 8 + r) * 8 + ctid) * 40 + wl];
                    bf[1] = sy[((kw * 8 + r) * 8 + ctid + 4) * 40 + wl];
                    mma_tf32(accK[0][f], aK[0], bf);
                    mma_tf32(accK[1][f], aK[1], bf);
                    mma_tf32(accV[0][f], aV[0], bf);
                    mma_tf32(accV[1][f], aV[1], bf);
                }
            }
            __syncthreads();

#pragma unroll
            for (int j = 0; j < 4; j++) pin[j] = pin2[j];
        }

#pragma unroll
        for (int rm = 0; rm < 2; rm++) {
#pragma unroll
            for (int f = 0; f < 4; f++) {
                int coA = co0 + co_base + rm * 16 + gid;
                int coB = coA + 8;
                int px  = px_base + f * 8 + 2 * ctid;
                int n   = (h0 + (px >> 5)) * WK + (px & 31);
                size_t oA = ((size_t)b * CCH + coA) * MM + n;
                size_t oB = ((size_t)b * CCH + coB) * MM + n;
                float bkA = bK[coA], bkB = bK[coB];
                float bvA = bV[coA], bvB = bV[coB];
                float2 kA = {accK[rm][f][0] + bkA, accK[rm][f][1] + bkA};
                float2 kB = {accK[rm][f][2] + bkB, accK[rm][f][3] + bkB};
                float2 vA = {accV[rm][f][0] + bvA, accV[rm][f][1] + bvA};
                float2 vB = {accV[rm][f][2] + bvB, accV[rm][f][3] + bvB};
                *reinterpret_cast<float2*>(&outK[oA]) = kA;
                *reinterpret_cast<float2*>(&outK[oB]) = kB;
                *reinterpret_cast<float2*>(&outV[oA]) = vA;
                *reinterpret_cast<float2*>(&outV[oB]) = vB;
            }
        }
    } else {
        // ============ conv3 path (bf16, 4 rows/block, packed input) ========
        const int px_base = (w & 3) * 64;
        const int d   = bx - 256;        // 0..511
        const int h0  = (d & 15) * 4;
        const int co0 = ((d >> 4) & 3) * 64;
        const int b   = d >> 6;

        u32* sxt = smem_u;               // 6*8*72 = 3456
        u32* swt = smem_u + 3456;        // 8*9*72 = 5184

        float acc[2][8][4];
#pragma unroll
        for (int i = 0; i < 2; i++)
#pragma unroll
            for (int j = 0; j < 8; j++)
#pragma unroll
                for (int l = 0; l < 4; l++) acc[i][j][l] = 0.f;

        const u32* xpb = xp + (size_t)b * 128 * NN;

        // zero halo columns once (cols 0 and 65 of 6x8 rows)
        if (tid < 96) {
            int r  = tid / 16;
            int c2 = (tid >> 1) & 7;
            int side = tid & 1;
            sxt[(r * 8 + c2) * 72 + side * 65] = 0;
        }

        // staging: 6 rows x 8 c2 x 16 uint4 = 768 uint4 -> 3 per thread
        uint4 pin[3], pin2[3];

#define C3_LOAD(dst, CI0)                                                    \
        {                                                                    \
            _Pragma("unroll")                                                \
            for (int j = 0; j < 3; j++) {                                    \
                int idx = tid + j * 256;                                     \
                int r  = idx >> 7;                                           \
                int c2 = (idx >> 4) & 7;                                     \
                int q  = idx & 15;                                           \
                int gh = h0 - 1 + r;                                         \
                uint4 v = {0u, 0u, 0u, 0u};                                  \
                if ((unsigned)gh < HH)                                       \
                    v = *reinterpret_cast<const uint4*>(                     \
                        &xpb[(size_t)(((CI0) >> 1) + c2) * NN + gh * WW + q * 4]); \
                dst[j] = v;                                                  \
            }                                                                \
        }

        C3_LOAD(pin, 0);

        for (int ci0 = 0; ci0 < CCH; ci0 += 16) {
#pragma unroll
            for (int j = 0; j < 3; j++) {
                int idx = tid + j * 256;
                int r  = idx >> 7;
                int c2 = (idx >> 4) & 7;
                int q  = idx & 15;
                u32* dd = &sxt[(r * 8 + c2) * 72 + 1 + q * 4];
                dd[0] = pin[j].x; dd[1] = pin[j].y; dd[2] = pin[j].z; dd[3] = pin[j].w;
            }
            for (int i = tid; i < 8 * 9 * 16; i += 256) {
                int k   = i / 128;
                int c2  = (i >> 4) & 7;
                int co4 = (i & 15) * 4;
                uint4 v = *reinterpret_cast<const uint4*>(
                    &wt3[((size_t)k * 128 + (ci0 >> 1) + c2) * 256 + co0 + co4]);
                *reinterpret_cast<uint4*>(&swt[(c2 * 9 + k) * 72 + co4]) = v;
            }
            __syncthreads();

            if (ci0 + 16 < CCH) C3_LOAD(pin2, ci0 + 16);

#pragma unroll
            for (int k = 0; k < 9; k++) {
                const int kh = k / 3, kw = k % 3;
                u32 a[2][4];
#pragma unroll
                for (int rm = 0; rm < 2; rm++) {
                    int cof = co_base + rm * 16;
                    a[rm][0] = swt[((ctid) * 9 + k) * 72 + cof + gid];
                    a[rm][1] = swt[((ctid) * 9 + k) * 72 + cof + gid + 8];
                    a[rm][2] = swt[((ctid + 4) * 9 + k) * 72 + cof + gid];
                    a[rm][3] = swt[((ctid + 4) * 9 + k) * 72 + cof + gid + 8];
                }
#pragma unroll
                for (int f = 0; f < 8; f++) {
                    int px = px_base + f * 8 + gid;
                    int rl = px >> 6;           // 0..3
                    int wc = (px & 63) + kw;
                    u32 bf[2];
                    bf[0] = sxt[((rl + kh) * 8 + ctid) * 72 + wc];
                    bf[1] = sxt[((rl + kh) * 8 + ctid + 4) * 72 + wc];
                    mma_bf16(acc[0][f], a[0], bf);
                    mma_bf16(acc[1][f], a[1], bf);
                }
            }
            __syncthreads();

            pin[0] = pin2[0]; pin[1] = pin2[1]; pin[2] = pin2[2];
        }

#pragma unroll
        for (int rm = 0; rm < 2; rm++) {
#pragma unroll
            for (int f = 0; f < 8; f++) {
                int coA = co0 + co_base + rm * 16 + gid;
                int coB = coA + 8;
                int px  = px_base + f * 8 + 2 * ctid;
                int n   = (h0 + (px >> 6)) * WW + (px & 63);
                float bA = bq[coA], bB = bq[coB];
                float2 sA = {acc[rm][f][0] + bA, acc[rm][f][1] + bA};
                float2 sB = {acc[rm][f][2] + bB, acc[rm][f][3] + bB};
                *reinterpret_cast<float2*>(&outQ[((size_t)b * CCH + coA) * NN + n]) = sA;
                *reinterpret_cast<float2*>(&outQ[((size_t)b * CCH + coB) * NN + n]) = sB;
            }
        }
    }
}

// ---------------------------------------------------------------------------
// GroupNorm + affine + SiLU, in place. Dual-buffer variant.
// ---------------------------------------------------------------------------
__global__ __launch_bounds__(512) void gn_silu_kernel(
    float* __restrict__ buf0, float* __restrict__ buf1,
    const float* __restrict__ scale0, const float* __restrict__ bias0,
    const float* __restrict__ scale1, const float* __restrict__ bias1,
    int S)
{
    int blk = blockIdx.x;
    float* buf = buf0;
    const float* scale = scale0;
    const float* bias  = bias0;
    if (buf1 != nullptr && blk >= 256) {
        blk -= 256; buf = buf1; scale = scale1; bias = bias1;
    }
    const int b = blk >> 5;
    const int g = blk & 31;
    float* base = buf + ((size_t)b * CCH + g * 8) * S;
    float4* p4 = reinterpret_cast<float4*>(base);
    const int tot4 = (8 * S) >> 2;
    const int tid = threadIdx.x;

    float s = 0.f, ss = 0.f;
    for (int i = tid; i < tot4; i += 512) {
        float4 v = p4[i];
        s += v.x + v.y + v.z + v.w;
        ss = fmaf(v.x, v.x, ss);
        ss = fmaf(v.y, v.y, ss);
        ss = fmaf(v.z, v.z, ss);
        ss = fmaf(v.w, v.w, ss);
    }
    __shared__ float r1[512], r2[512];
    r1[tid] = s; r2[tid] = ss;
    __syncthreads();
    for (int st = 256; st > 0; st >>= 1) {
        if (tid < st) { r1[tid] += r1[tid + st]; r2[tid] += r2[tid + st]; }
        __syncthreads();
    }
    const float tot = (float)(8 * S);
    const float mu   = r1[0] / tot;
    const float var  = r2[0] / tot - mu * mu;
    const float rstd = rsqrtf(var + 1e-5f);

    const int s4 = S >> 2;
    for (int i = tid; i < tot4; i += 512) {
        int c = g * 8 + i / s4;
        float sc = scale[c] * rstd, bi = bias[c] - mu * scale[c] * rstd;
        float4 v = p4[i];
        v.x = fmaf(v.x, sc, bi);
        v.y = fmaf(v.y, sc, bi);
        v.z = fmaf(v.z, sc, bi);
        v.w = fmaf(v.w, sc, bi);
        v.x = v.x / (1.f + __expf(-v.x));
        v.y = v.y / (1.f + __expf(-v.y));
        v.z = v.z / (1.f + __expf(-v.z));
        v.w = v.w / (1.f + __expf(-v.w));
        p4[i] = v;
    }
}

// ---------------------------------------------------------------------------
// E = (1/16) Q^T K  (bf16 m16n8k16), staged loads double-buffered.
// grid: (MM/128=8, NN/128=32, B=8)
// ---------------------------------------------------------------------------
__global__ __launch_bounds__(256, 2) void gemm_qk_mma(
    const float* __restrict__ Q, const float* __restrict__ K,
    float* __restrict__ E)
{
    const int mb = blockIdx.x * 128;
    const int nb = blockIdx.y * 128;
    const int b  = blockIdx.z;
    const int tid  = threadIdx.x;
    const int lane = tid & 31;
    const int w    = tid >> 5;
    const int gid  = lane >> 2;
    const int ctid = lane & 3;
    const int m_base = (w & 1) * 64;
    const int n_base = (w >> 1) * 32;

    __shared__ u32 sq2[8 * 136];
    __shared__ u32 sk2[8 * 136];

    float acc[2][8][4];
#pragma unroll
    for (int i = 0; i < 2; i++)
#pragma unroll
        for (int j = 0; j < 8; j++)
#pragma unroll
            for (int l = 0; l < 4; l++) acc[i][j][l] = 0.f;

    const float* Qb = Q + (size_t)b * CCH * NN + nb;
    const float* Kb = K + (size_t)b * CCH * MM + mb;

    const int kc  = tid >> 5;
    const int col = (lane) * 4;

    float4 pq0, pq1, pk0, pk1, nq0, nq1, nk0, nk1;

#define QK_LOAD(q0, q1, k0, k1, C0)                                                        \
    {                                                                                      \
        q0 = *reinterpret_cast<const float4*>(&Qb[(size_t)((C0) + 2 * kc) * NN + col]);     \
        q1 = *reinterpret_cast<const float4*>(&Qb[(size_t)((C0) + 2 * kc + 1) * NN + col]); \
        k0 = *reinterpret_cast<const float4*>(&Kb[(size_t)((C0) + 2 * kc) * MM + col]);     \
        k1 = *reinterpret_cast<const float4*>(&Kb[(size_t)((C0) + 2 * kc + 1) * MM + col]); \
    }

    QK_LOAD(pq0, pq1, pk0, pk1, 0);

    for (int c0 = 0; c0 < CCH; c0 += 16) {
        uint4 qs = {pkbf(pq0.x, pq1.x), pkbf(pq0.y, pq1.y),
                    pkbf(pq0.z, pq1.z), pkbf(pq0.w, pq1.w)};
        uint4 ks = {pkbf(pk0.x, pk1.x), pkbf(pk0.y, pk1.y),
                    pkbf(pk0.z, pk1.z), pkbf(pk0.w, pk1.w)};
        *reinterpret_cast<uint4*>(&sq2[kc * 136 + col]) = qs;
        *reinterpret_cast<uint4*>(&sk2[kc * 136 + col]) = ks;
        __syncthreads();

        if (c0 + 16 < CCH) QK_LOAD(nq0, nq1, nk0, nk1, c0 + 16);

        u32 a[2][4];
#pragma unroll
        for (int rm = 0; rm < 2; rm++) {
            int n0 = n_base + rm * 16;
            a[rm][0] = sq2[ctid * 136 + n0 + gid];
            a[rm][1] = sq2[ctid * 136 + n0 + gid + 8];
            a[rm][2] = sq2[(ctid + 4) * 136 + n0 + gid];
            a[rm][3] = sq2[(ctid + 4) * 136 + n0 + gid + 8];
        }
#pragma unroll
        for (int f = 0; f < 8; f++) {
            u32 bf[2];
            bf[0] = sk2[ctid * 136 + m_base + f * 8 + gid];
            bf[1] = sk2[(ctid + 4) * 136 + m_base + f * 8 + gid];
            mma_bf16(acc[0][f], a[0], bf);
            mma_bf16(acc[1][f], a[1], bf);
        }
        __syncthreads();

        pq0 = nq0; pq1 = nq1; pk0 = nk0; pk1 = nk1;
    }

    const float scale = 0.0625f;
    float* Eb = E + ((size_t)b * NN + nb) * MM + mb;
#pragma unroll
    for (int rm = 0; rm < 2; rm++) {
#pragma unroll
        for (int f = 0; f < 8; f++) {
            int r0 = n_base + rm * 16 + gid;
            int cc = m_base + f * 8 + 2 * ctid;
            float2 s0 = {acc[rm][f][0] * scale, acc[rm][f][1] * scale};
            float2 s1 = {acc[rm][f][2] * scale, acc[rm][f][3] * scale};
            *reinterpret_cast<float2*>(&Eb[(size_t)r0 * MM + cc])       = s0;
            *reinterpret_cast<float2*>(&Eb[(size_t)(r0 + 8) * MM + cc]) = s1;
        }
    }
}

// ---------------------------------------------------------------------------
// Softmax over last dim (M=1024), fp32 in -> packed bf16x2 out (m-pairs).
// ---------------------------------------------------------------------------
__global__ __launch_bounds__(256) void softmax_kernel(
    const float* __restrict__ E, u32* __restrict__ A)
{
    const int warp = threadIdx.x >> 5;
    const int lane = threadIdx.x & 31;
    const size_t row = (size_t)blockIdx.x * 8 + warp;
    const float4* p = reinterpret_cast<const float4*>(E + row * MM);
    u32* pa = A + row * (MM / 2);

    float4 v[8];
    float mx = -1e30f;
#pragma unroll
    for (int i = 0; i < 8; i++) {
        v[i] = p[lane + 32 * i];
        mx = fmaxf(mx, fmaxf(fmaxf(v[i].x, v[i].y), fmaxf(v[i].z, v[i].w)));
    }
#pragma unroll
    for (int o = 16; o > 0; o >>= 1)
        mx = fmaxf(mx, __shfl_xor_sync(0xFFFFFFFFu, mx, o));

    float sum = 0.f;
#pragma unroll
    for (int i = 0; i < 8; i++) {
        v[i].x = __expf(v[i].x - mx);
        v[i].y = __expf(v[i].y - mx);
        v[i].z = __expf(v[i].z - mx);
        v[i].w = __expf(v[i].w - mx);
        sum += v[i].x + v[i].y + v[i].z + v[i].w;
    }
#pragma unroll
    for (int o = 16; o > 0; o >>= 1)
        sum += __shfl_xor_sync(0xFFFFFFFFu, sum, o);

    float inv = 1.f / sum;
#pragma unroll
    for (int i = 0; i < 8; i++) {
        uint2 st;
        st.x = pkbf(v[i].x * inv, v[i].y * inv);
        st.y = pkbf(v[i].z * inv, v[i].w * inv);
        *reinterpret_cast<uint2*>(&pa[2 * (lane + 32 * i)]) = st;
    }
}

// ---------------------------------------------------------------------------
// out = gamma * V A^T (bf16 m16n8k16). A read pre-packed bf16x2 (m-pairs).
// grid: (NN/128=32, CCH/128=2, B=8)
// ---------------------------------------------------------------------------
__global__ __launch_bounds__(256, 2) void gemm_av_mma(
    const float* __restrict__ V, const u32* __restrict__ A,
    const float* __restrict__ gamma, float* __restrict__ out)
{
    const int nb = blockIdx.x * 128;
    const int cb = blockIdx.y * 128;
    const int b  = blockIdx.z;
    const int tid  = threadIdx.x;
    const int lane = tid & 31;
    const int w    = tid >> 5;
    const int gid  = lane >> 2;
    const int ctid = lane & 3;
    const int n_base = (w & 1) * 64;
    const int c_base = (w >> 1) * 32;

    __shared__ u32 sv2[8 * 136];
    __shared__ u32 sa2[8 * 136];

    float acc[2][8][4];
#pragma unroll
    for (int i = 0; i < 2; i++)
#pragma unroll
        for (int j = 0; j < 8; j++)
#pragma unroll
            for (int l = 0; l < 4; l++) acc[i][j][l] = 0.f;

    const float* Vb = V + (size_t)b * CCH * MM;
    const u32* Ab = A + (size_t)b * NN * (MM / 2);

    const int row0 = tid >> 2, f0 = tid & 3;
    const int row1 = row0 + 64;

    float4 pv0, pv1, nv0, nv1;
    uint2 pa0, pa1, na0, na1;

#define AV_LOAD(v0, v1, a0v, a1v, M0)                                                           \
    {                                                                                           \
        v0  = *reinterpret_cast<const float4*>(&Vb[(size_t)(cb + row0) * MM + (M0) + f0 * 4]);   \
        v1  = *reinterpret_cast<const float4*>(&Vb[(size_t)(cb + row1) * MM + (M0) + f0 * 4]);   \
        a0v = *reinterpret_cast<const uint2*>(&Ab[(size_t)(nb + row0) * (MM / 2) + ((M0) >> 1) + f0 * 2]); \
        a1v = *reinterpret_cast<const uint2*>(&Ab[(size_t)(nb + row1) * (MM / 2) + ((M0) >> 1) + f0 * 2]); \
    }

    AV_LOAD(pv0, pv1, pa0, pa1, 0);

    for (int m0 = 0; m0 < MM; m0 += 16) {
        sv2[(f0 * 2) * 136 + row0]     = pkbf(pv0.x, pv0.y);
        sv2[(f0 * 2 + 1) * 136 + row0] = pkbf(pv0.z, pv0.w);
        sv2[(f0 * 2) * 136 + row1]     = pkbf(pv1.x, pv1.y);
        sv2[(f0 * 2 + 1) * 136 + row1] = pkbf(pv1.z, pv1.w);
        sa2[(f0 * 2) * 136 + row0]     = pa0.x;
        sa2[(f0 * 2 + 1) * 136 + row0] = pa0.y;
        sa2[(f0 * 2) * 136 + row1]     = pa1.x;
        sa2[(f0 * 2 + 1) * 136 + row1] = pa1.y;
        __syncthreads();

        if (m0 + 16 < MM) AV_LOAD(nv0, nv1, na0, na1, m0 + 16);

        u32 a[2][4];
#pragma unroll
        for (int rm = 0; rm < 2; rm++) {
            int c0 = c_base + rm * 16;
            a[rm][0] = sv2[ctid * 136 + c0 + gid];
            a[rm][1] = sv2[ctid * 136 + c0 + gid + 8];
            a[rm][2] = sv2[(ctid + 4) * 136 + c0 + gid];
            a[rm][3] = sv2[(ctid + 4) * 136 + c0 + gid + 8];
        }
#pragma unroll
        for (int f = 0; f < 8; f++) {
            u32 bf[2];
            bf[0] = sa2[ctid * 136 + n_base + f * 8 + gid];
            bf[1] = sa2[(ctid + 4) * 136 + n_base + f * 8 + gid];
            mma_bf16(acc[0][f], a[0], bf);
            mma_bf16(acc[1][f], a[1], bf);
        }
        __syncthreads();

        pv0 = nv0; pv1 = nv1; pa0 = na0; pa1 = na1;
    }

    const float gm = gamma[0];
#pragma unroll
    for (int rm = 0; rm < 2; rm++) {
#pragma unroll
        for (int f = 0; f < 8; f++) {
            int c0 = cb + c_base + rm * 16 + gid;
            int nn2 = nb + n_base + f * 8 + 2 * ctid;
            float2 s0 = {gm * acc[rm][f][0], gm * acc[rm][f][1]};
            float2 s1 = {gm * acc[rm][f][2], gm * acc[rm][f][3]};
            *reinterpret_cast<float2*>(&out[((size_t)b * CCH + c0) * NN + nn2])     = s0;
            *reinterpret_cast<float2*>(&out[((size_t)b * CCH + c0 + 8) * NN + nn2]) = s1;
        }
    }
}

// ---------------------------------------------------------------------------
extern "C" void kernel_launch(void* const* d_in, const int* in_sizes, int n_in,
                              void* d_out, int out_size)
{
    const float* x        = (const float*)d_in[0];
    const float* y        = (const float*)d_in[1];
    const float* Wq       = (const float*)d_in[2];
    const float* bq       = (const float*)d_in[3];
    const float* gq_scale = (const float*)d_in[4];
    const float* gq_bias  = (const float*)d_in[5];
    const float* Wk       = (const float*)d_in[6];
    const float* bk       = (const float*)d_in[7];
    const float* gk_scale = (const float*)d_in[8];
    const float* gk_bias  = (const float*)d_in[9];
    const float* Wv       = (const float*)d_in[10];
    const float* bv       = (const float*)d_in[11];
    const float* gv_scale = (const float*)d_in[12];
    const float* gv_bias  = (const float*)d_in[13];
    const float* gamma    = (const float*)d_in[14];
    float* out = (float*)d_out;

    float *qp = nullptr, *kp = nullptr, *vp = nullptr, *ep = nullptr;
    u32 *ap = nullptr, *xpp = nullptr, *wtp = nullptr, *wkp = nullptr, *wvp = nullptr;
    cudaGetSymbolAddress((void**)&qp, g_q);
    cudaGetSymbolAddress((void**)&kp, g_k);
    cudaGetSymbolAddress((void**)&vp, g_v);
    cudaGetSymbolAddress((void**)&ep, g_e);
    cudaGetSymbolAddress((void**)&ap, g_a);
    cudaGetSymbolAddress((void**)&xpp, g_xp);
    cudaGetSymbolAddress((void**)&wtp, g_wt3);
    cudaGetSymbolAddress((void**)&wkp, g_wk2);
    cudaGetSymbolAddress((void**)&wvp, g_wv2);

    xpack_kernel<<<(BATCH * 128 * NN + 255) / 256, 256>>>(x, xpp);
    transpose_w3<<<(9 * 128 * 256 + 255) / 256, 256>>>(Wq, wtp);
    transpose_w2<<<(4 * 256 * 256 + 255) / 256, 256>>>(Wk, Wv, wkp, wvp);

    conv_fused<<<768, 256>>>(wtp, xpp, bq, qp, wkp, wvp, y, bk, bv, kp, vp);

    gn_silu_kernel<<<BATCH * 64, 512>>>(kp, vp, gk_scale, gk_bias,
                                        gv_scale, gv_bias, MM);
    gn_silu_kernel<<<BATCH * 32, 512>>>(qp, nullptr, gq_scale, gq_bias,
                                        nullptr, nullptr, NN);

    gemm_qk_mma<<<dim3(MM / 128, NN / 128, BATCH), 256>>>(qp, kp, ep);
    softmax_kernel<<<BATCH * NN / 8, 256>>>(ep, ap);
    gemm_av_mma<<<dim3(NN / 128, CCH / 128, BATCH), 256>>>(vp, ap, gamma, out);
}

// round 17
// speedup vs baseline: 1.5269x; 1.0452x over previous
#include <cuda_runtime.h>
#include <math.h>

#define BATCH 8
#define CCH   256
#define HH    64
#define WW    64
#define NN    4096   // HH*WW
#define MM    1024   // (HH/2)*(WW/2)
#define HK    32
#define WK    32

typedef unsigned long long u64;
typedef unsigned int u32;

__device__ __forceinline__ u32 f2tf(float f) {
    u32 u; asm("cvt.rna.tf32.f32 %0,%1;" : "=r"(u) : "f"(f)); return u;
}
// pack (lo, hi) floats -> bf16x2 word (lo in low half)
__device__ __forceinline__ u32 pkbf(float lo, float hi) {
    u32 d; asm("cvt.rn.bf16x2.f32 %0,%1,%2;" : "=r"(d) : "f"(hi), "f"(lo)); return d;
}
__device__ __forceinline__ float2 upbf(u32 w) {
    float2 f;
    f.x = __uint_as_float(w << 16);
    f.y = __uint_as_float(w & 0xffff0000u);
    return f;
}
__device__ __forceinline__ void mma_tf32(float* d, const u32* a, const u32* b) {
    asm volatile(
        "mma.sync.aligned.m16n8k8.row.col.f32.tf32.tf32.f32 "
        "{%0,%1,%2,%3},{%4,%5,%6,%7},{%8,%9},{%0,%1,%2,%3};"
        : "+f"(d[0]), "+f"(d[1]), "+f"(d[2]), "+f"(d[3])
        : "r"(a[0]), "r"(a[1]), "r"(a[2]), "r"(a[3]), "r"(b[0]), "r"(b[1]));
}
__device__ __forceinline__ void mma_bf16(float* d, const u32* a, const u32* b) {
    asm volatile(
        "mma.sync.aligned.m16n8k16.row.col.f32.bf16.bf16.f32 "
        "{%0,%1,%2,%3},{%4,%5,%6,%7},{%8,%9},{%0,%1,%2,%3};"
        : "+f"(d[0]), "+f"(d[1]), "+f"(d[2]), "+f"(d[3])
        : "r"(a[0]), "r"(a[1]), "r"(a[2]), "r"(a[3]), "r"(b[0]), "r"(b[1]));
}

// Scratch
__device__ float g_q[(size_t)BATCH * CCH * NN];   // 32 MB
__device__ float g_k[(size_t)BATCH * CCH * MM];   // 8 MB
__device__ float g_v[(size_t)BATCH * CCH * MM];   // 8 MB
__device__ u32   g_a[(size_t)BATCH * NN * (MM/2)]; // 64 MB (expE, bf16x2 m-pairs)
__device__ float g_rs[(size_t)BATCH * NN];        // 128 KB row sums
__device__ u32   g_xp[(size_t)BATCH * 128 * NN];  // 16 MB (x packed bf16x2)
__device__ u32   g_wt3[9 * 128 * 256];            // Wq [k][ci2][co] bf16x2
__device__ u32   g_wk2[4 * 256 * 256];            // Wk transposed, tf32
__device__ u32   g_wv2[4 * 256 * 256];            // Wv transposed, tf32

// ---------------------------------------------------------------------------
__global__ __launch_bounds__(256) void xpack_kernel(
    const float* __restrict__ x, u32* __restrict__ xp)
{
    size_t i = (size_t)blockIdx.x * 256 + threadIdx.x;
    if (i < (size_t)BATCH * 128 * NN) {
        int hw  = i & (NN - 1);
        int c2  = (i >> 12) & 127;
        int b   = i >> 19;
        size_t base = ((size_t)b * CCH + 2 * c2) * NN + hw;
        xp[i] = pkbf(x[base], x[base + NN]);
    }
}

__global__ __launch_bounds__(256) void transpose_w3(
    const float* __restrict__ Wt, u32* __restrict__ wt3)
{
    int i = blockIdx.x * 256 + threadIdx.x;
    if (i < 9 * 128 * 256) {
        int co  = i & 255;
        int ci2 = (i >> 8) & 127;
        int k   = i >> 15;
        float lo = Wt[((size_t)co * 256 + 2 * ci2) * 9 + k];
        float hi = Wt[((size_t)co * 256 + 2 * ci2 + 1) * 9 + k];
        wt3[i] = pkbf(lo, hi);
    }
}

__global__ __launch_bounds__(256) void transpose_w2(
    const float* __restrict__ Wk, const float* __restrict__ Wv,
    u32* __restrict__ wk2, u32* __restrict__ wv2)
{
    int i = blockIdx.x * 256 + threadIdx.x;
    if (i < 4 * 256 * 256) {
        int co = i & 255;
        int ci = (i >> 8) & 255;
        int k  = i >> 16;
        wk2[i] = f2tf(Wk[((size_t)co * 256 + ci) * 4 + k]);
        wv2[i] = f2tf(Wv[((size_t)co * 256 + ci) * 4 + k]);
    }
}

// ---------------------------------------------------------------------------
// FUSED conv launch, LJF mapping over 768 blocks (unchanged R16).
// ---------------------------------------------------------------------------
__global__ __launch_bounds__(256, 2) void conv_fused(
    const u32* __restrict__ wt3, const u32* __restrict__ xp,
    const float* __restrict__ bq, float* __restrict__ outQ,
    const u32* __restrict__ wtK, const u32* __restrict__ wtV,
    const float* __restrict__ y,
    const float* __restrict__ bK, const float* __restrict__ bV,
    float* __restrict__ outK, float* __restrict__ outV)
{
    __shared__ u32 smem_u[9856];

    const int bx = blockIdx.x;
    const int tid  = threadIdx.x;
    const int lane = tid & 31;
    const int w    = tid >> 5;
    const int gid  = lane >> 2;
    const int ctid = lane & 3;
    const int co_base = (w >> 2) * 32;

    if (bx < 256) {
        const int px_base = (w & 3) * 32;
        const int c   = bx;
        const int h0  = (c & 7) * 4;
        const int co0 = ((c >> 3) & 3) * 64;
        const int b   = c >> 5;

        u32* sy  = smem_u;
        u32* swK = smem_u + 5120;
        u32* swV = smem_u + 7488;

        float accK[2][4][4], accV[2][4][4];
#pragma unroll
        for (int i = 0; i < 2; i++)
#pragma unroll
            for (int j = 0; j < 4; j++)
#pragma unroll
                for (int l = 0; l < 4; l++) { accK[i][j][l] = 0.f; accV[i][j][l] = 0.f; }

        const float* yb = y + (size_t)b * CCH * (HH * WW);
        const int ih0 = h0 * 2;

        float4 pin[4], pin2[4];

#define C2_LOAD(dst, CI0)                                                   \
        {                                                                   \
            _Pragma("unroll")                                               \
            for (int j = 0; j < 4; j++) {                                   \
                int i  = tid + j * 256;                                     \
                int r  = i >> 7;                                            \
                int ci = (i >> 4) & 7;                                      \
                int c4 = (i & 15) * 4;                                      \
                dst[j] = *reinterpret_cast<const float4*>(                  \
                    &yb[(size_t)((CI0) + ci) * (HH * WW) + (ih0 + r) * WW + c4]); \
            }                                                               \
        }

        C2_LOAD(pin, 0);

        for (int ci0 = 0; ci0 < CCH; ci0 += 8) {
#pragma unroll
            for (int j = 0; j < 4; j++) {
                int i  = tid + j * 256;
                int r  = i >> 7;
                int ci = (i >> 4) & 7;
                int c4 = (i & 15) * 4;
                float4 v = pin[j];
                u32* even = &sy[((0 * 8 + r) * 8 + ci) * 40 + (c4 >> 1)];
                u32* odd  = &sy[((8 + r) * 8 + ci) * 40 + (c4 >> 1)];
                even[0] = f2tf(v.x); odd[0] = f2tf(v.y);
                even[1] = f2tf(v.z); odd[1] = f2tf(v.w);
            }
            for (int i = tid; i < 8 * 4 * 16; i += 256) {
                int k   = i / 128;
                int ci  = (i >> 4) & 7;
                int co4 = (i & 15) * 4;
                size_t off = ((size_t)k * 256 + ci0 + ci) * 256 + co0 + co4;
                uint4 vk = *reinterpret_cast<const uint4*>(&wtK[off]);
                uint4 vv = *reinterpret_cast<const uint4*>(&wtV[off]);
                u32* dk = &swK[(ci * 4 + k) * 74 + co4];
                dk[0] = vk.x; dk[1] = vk.y; dk[2] = vk.z; dk[3] = vk.w;
                u32* dv = &swV[(ci * 4 + k) * 74 + co4];
                dv[0] = vv.x; dv[1] = vv.y; dv[2] = vv.z; dv[3] = vv.w;
            }
            __syncthreads();

            if (ci0 + 8 < CCH) C2_LOAD(pin2, ci0 + 8);

#pragma unroll
            for (int k = 0; k < 4; k++) {
                const int kh = k >> 1, kw = k & 1;
                u32 aK[2][4], aV[2][4];
#pragma unroll
                for (int rm = 0; rm < 2; rm++) {
                    int cof = co_base + rm * 16;
                    int r0 = (ctid * 4 + k) * 74 + cof;
                    int r1 = ((ctid + 4) * 4 + k) * 74 + cof;
                    aK[rm][0] = swK[r0 + gid];     aK[rm][1] = swK[r0 + gid + 8];
                    aK[rm][2] = swK[r1 + gid];     aK[rm][3] = swK[r1 + gid + 8];
                    aV[rm][0] = swV[r0 + gid];     aV[rm][1] = swV[r0 + gid + 8];
                    aV[rm][2] = swV[r1 + gid];     aV[rm][3] = swV[r1 + gid + 8];
                }
#pragma unroll
                for (int f = 0; f < 4; f++) {
                    int px = px_base + f * 8 + gid;
                    int r  = 2 * (px >> 5) + kh;
                    int wl = px & 31;
                    u32 bf[2];
                    bf[0] = sy[((kw * 8 + r) * 8 + ctid) * 40 + wl];
                    bf[1] = sy[((kw * 8 + r) * 8 + ctid + 4) * 40 + wl];
                    mma_tf32(accK[0][f], aK[0], bf);
                    mma_tf32(accK[1][f], aK[1], bf);
                    mma_tf32(accV[0][f], aV[0], bf);
                    mma_tf32(accV[1][f], aV[1], bf);
                }
            }
            __syncthreads();

#pragma unroll
            for (int j = 0; j < 4; j++) pin[j] = pin2[j];
        }

#pragma unroll
        for (int rm = 0; rm < 2; rm++) {
#pragma unroll
            for (int f = 0; f < 4; f++) {
                int coA = co0 + co_base + rm * 16 + gid;
                int coB = coA + 8;
                int px  = px_base + f * 8 + 2 * ctid;
                int n   = (h0 + (px >> 5)) * WK + (px & 31);
                size_t oA = ((size_t)b * CCH + coA) * MM + n;
                size_t oB = ((size_t)b * CCH + coB) * MM + n;
                float bkA = bK[coA], bkB = bK[coB];
                float bvA = bV[coA], bvB = bV[coB];
                float2 kA = {accK[rm][f][0] + bkA, accK[rm][f][1] + bkA};
                float2 kB = {accK[rm][f][2] + bkB, accK[rm][f][3] + bkB};
                float2 vA = {accV[rm][f][0] + bvA, accV[rm][f][1] + bvA};
                float2 vB = {accV[rm][f][2] + bvB, accV[rm][f][3] + bvB};
                *reinterpret_cast<float2*>(&outK[oA]) = kA;
                *reinterpret_cast<float2*>(&outK[oB]) = kB;
                *reinterpret_cast<float2*>(&outV[oA]) = vA;
                *reinterpret_cast<float2*>(&outV[oB]) = vB;
            }
        }
    } else {
        const int px_base = (w & 3) * 64;
        const int d   = bx - 256;
        const int h0  = (d & 15) * 4;
        const int co0 = ((d >> 4) & 3) * 64;
        const int b   = d >> 6;

        u32* sxt = smem_u;
        u32* swt = smem_u + 3456;

        float acc[2][8][4];
#pragma unroll
        for (int i = 0; i < 2; i++)
#pragma unroll
            for (int j = 0; j < 8; j++)
#pragma unroll
                for (int l = 0; l < 4; l++) acc[i][j][l] = 0.f;

        const u32* xpb = xp + (size_t)b * 128 * NN;

        if (tid < 96) {
            int r  = tid / 16;
            int c2 = (tid >> 1) & 7;
            int side = tid & 1;
            sxt[(r * 8 + c2) * 72 + side * 65] = 0;
        }

        uint4 pin[3], pin2[3];

#define C3_LOAD(dst, CI0)                                                    \
        {                                                                    \
            _Pragma("unroll")                                                \
            for (int j = 0; j < 3; j++) {                                    \
                int idx = tid + j * 256;                                     \
                int r  = idx >> 7;                                           \
                int c2 = (idx >> 4) & 7;                                     \
                int q  = idx & 15;                                           \
                int gh = h0 - 1 + r;                                         \
                uint4 v = {0u, 0u, 0u, 0u};                                  \
                if ((unsigned)gh < HH)                                       \
                    v = *reinterpret_cast<const uint4*>(                     \
                        &xpb[(size_t)(((CI0) >> 1) + c2) * NN + gh * WW + q * 4]); \
                dst[j] = v;                                                  \
            }                                                                \
        }

        C3_LOAD(pin, 0);

        for (int ci0 = 0; ci0 < CCH; ci0 += 16) {
#pragma unroll
            for (int j = 0; j < 3; j++) {
                int idx = tid + j * 256;
                int r  = idx >> 7;
                int c2 = (idx >> 4) & 7;
                int q  = idx & 15;
                u32* dd = &sxt[(r * 8 + c2) * 72 + 1 + q * 4];
                dd[0] = pin[j].x; dd[1] = pin[j].y; dd[2] = pin[j].z; dd[3] = pin[j].w;
            }
            for (int i = tid; i < 8 * 9 * 16; i += 256) {
                int k   = i / 128;
                int c2  = (i >> 4) & 7;
                int co4 = (i & 15) * 4;
                uint4 v = *reinterpret_cast<const uint4*>(
                    &wt3[((size_t)k * 128 + (ci0 >> 1) + c2) * 256 + co0 + co4]);
                *reinterpret_cast<uint4*>(&swt[(c2 * 9 + k) * 72 + co4]) = v;
            }
            __syncthreads();

            if (ci0 + 16 < CCH) C3_LOAD(pin2, ci0 + 16);

#pragma unroll
            for (int k = 0; k < 9; k++) {
                const int kh = k / 3, kw = k % 3;
                u32 a[2][4];
#pragma unroll
                for (int rm = 0; rm < 2; rm++) {
                    int cof = co_base + rm * 16;
                    a[rm][0] = swt[((ctid) * 9 + k) * 72 + cof + gid];
                    a[rm][1] = swt[((ctid) * 9 + k) * 72 + cof + gid + 8];
                    a[rm][2] = swt[((ctid + 4) * 9 + k) * 72 + cof + gid];
                    a[rm][3] = swt[((ctid + 4) * 9 + k) * 72 + cof + gid + 8];
                }
#pragma unroll
                for (int f = 0; f < 8; f++) {
                    int px = px_base + f * 8 + gid;
                    int rl = px >> 6;
                    int wc = (px & 63) + kw;
                    u32 bf[2];
                    bf[0] = sxt[((rl + kh) * 8 + ctid) * 72 + wc];
                    bf[1] = sxt[((rl + kh) * 8 + ctid + 4) * 72 + wc];
                    mma_bf16(acc[0][f], a[0], bf);
                    mma_bf16(acc[1][f], a[1], bf);
                }
            }
            __syncthreads();

            pin[0] = pin2[0]; pin[1] = pin2[1]; pin[2] = pin2[2];
        }

#pragma unroll
        for (int rm = 0; rm < 2; rm++) {
#pragma unroll
            for (int f = 0; f < 8; f++) {
                int coA = co0 + co_base + rm * 16 + gid;
                int coB = coA + 8;
                int px  = px_base + f * 8 + 2 * ctid;
                int n   = (h0 + (px >> 6)) * WW + (px & 63);
                float bA = bq[coA], bB = bq[coB];
                float2 sA = {acc[rm][f][0] + bA, acc[rm][f][1] + bA};
                float2 sB = {acc[rm][f][2] + bB, acc[rm][f][3] + bB};
                *reinterpret_cast<float2*>(&outQ[((size_t)b * CCH + coA) * NN + n]) = sA;
                *reinterpret_cast<float2*>(&outQ[((size_t)b * CCH + coB) * NN + n]) = sB;
            }
        }
    }
}

// ---------------------------------------------------------------------------
// GroupNorm + affine + SiLU, in place. Dual-buffer variant.
// ---------------------------------------------------------------------------
__global__ __launch_bounds__(512) void gn_silu_kernel(
    float* __restrict__ buf0, float* __restrict__ buf1,
    const float* __restrict__ scale0, const float* __restrict__ bias0,
    const float* __restrict__ scale1, const float* __restrict__ bias1,
    int S)
{
    int blk = blockIdx.x;
    float* buf = buf0;
    const float* scale = scale0;
    const float* bias  = bias0;
    if (buf1 != nullptr && blk >= 256) {
        blk -= 256; buf = buf1; scale = scale1; bias = bias1;
    }
    const int b = blk >> 5;
    const int g = blk & 31;
    float* base = buf + ((size_t)b * CCH + g * 8) * S;
    float4* p4 = reinterpret_cast<float4*>(base);
    const int tot4 = (8 * S) >> 2;
    const int tid = threadIdx.x;

    float s = 0.f, ss = 0.f;
    for (int i = tid; i < tot4; i += 512) {
        float4 v = p4[i];
        s += v.x + v.y + v.z + v.w;
        ss = fmaf(v.x, v.x, ss);
        ss = fmaf(v.y, v.y, ss);
        ss = fmaf(v.z, v.z, ss);
        ss = fmaf(v.w, v.w, ss);
    }
    __shared__ float r1[512], r2[512];
    r1[tid] = s; r2[tid] = ss;
    __syncthreads();
    for (int st = 256; st > 0; st >>= 1) {
        if (tid < st) { r1[tid] += r1[tid + st]; r2[tid] += r2[tid + st]; }
        __syncthreads();
    }
    const float tot = (float)(8 * S);
    const float mu   = r1[0] / tot;
    const float var  = r2[0] / tot - mu * mu;
    const float rstd = rsqrtf(var + 1e-5f);

    const int s4 = S >> 2;
    for (int i = tid; i < tot4; i += 512) {
        int c = g * 8 + i / s4;
        float sc = scale[c] * rstd, bi = bias[c] - mu * scale[c] * rstd;
        float4 v = p4[i];
        v.x = fmaf(v.x, sc, bi);
        v.y = fmaf(v.y, sc, bi);
        v.z = fmaf(v.z, sc, bi);
        v.w = fmaf(v.w, sc, bi);
        v.x = v.x / (1.f + __expf(-v.x));
        v.y = v.y / (1.f + __expf(-v.y));
        v.z = v.z / (1.f + __expf(-v.z));
        v.w = v.w / (1.f + __expf(-v.w));
        p4[i] = v;
    }
}

// ---------------------------------------------------------------------------
// A = exp((1/16) Q^T K)  (bf16 m16n8k16) -> bf16x2 m-pairs directly.
// No max subtraction (logits O(1), no overflow). grid: (8, 32, 8)
// ---------------------------------------------------------------------------
__global__ __launch_bounds__(256, 2) void gemm_qk_mma(
    const float* __restrict__ Q, const float* __restrict__ K,
    u32* __restrict__ A)
{
    const int mb = blockIdx.x * 128;
    const int nb = blockIdx.y * 128;
    const int b  = blockIdx.z;
    const int tid  = threadIdx.x;
    const int lane = tid & 31;
    const int w    = tid >> 5;
    const int gid  = lane >> 2;
    const int ctid = lane & 3;
    const int m_base = (w & 1) * 64;
    const int n_base = (w >> 1) * 32;

    __shared__ u32 sq2[8 * 136];
    __shared__ u32 sk2[8 * 136];

    float acc[2][8][4];
#pragma unroll
    for (int i = 0; i < 2; i++)
#pragma unroll
        for (int j = 0; j < 8; j++)
#pragma unroll
            for (int l = 0; l < 4; l++) acc[i][j][l] = 0.f;

    const float* Qb = Q + (size_t)b * CCH * NN + nb;
    const float* Kb = K + (size_t)b * CCH * MM + mb;

    const int kc  = tid >> 5;
    const int col = (lane) * 4;

    float4 pq0, pq1, pk0, pk1, nq0, nq1, nk0, nk1;

#define QK_LOAD(q0, q1, k0, k1, C0)                                                        \
    {                                                                                      \
        q0 = *reinterpret_cast<const float4*>(&Qb[(size_t)((C0) + 2 * kc) * NN + col]);     \
        q1 = *reinterpret_cast<const float4*>(&Qb[(size_t)((C0) + 2 * kc + 1) * NN + col]); \
        k0 = *reinterpret_cast<const float4*>(&Kb[(size_t)((C0) + 2 * kc) * MM + col]);     \
        k1 = *reinterpret_cast<const float4*>(&Kb[(size_t)((C0) + 2 * kc + 1) * MM + col]); \
    }

    QK_LOAD(pq0, pq1, pk0, pk1, 0);

    for (int c0 = 0; c0 < CCH; c0 += 16) {
        uint4 qs = {pkbf(pq0.x, pq1.x), pkbf(pq0.y, pq1.y),
                    pkbf(pq0.z, pq1.z), pkbf(pq0.w, pq1.w)};
        uint4 ks = {pkbf(pk0.x, pk1.x), pkbf(pk0.y, pk1.y),
                    pkbf(pk0.z, pk1.z), pkbf(pk0.w, pk1.w)};
        *reinterpret_cast<uint4*>(&sq2[kc * 136 + col]) = qs;
        *reinterpret_cast<uint4*>(&sk2[kc * 136 + col]) = ks;
        __syncthreads();

        if (c0 + 16 < CCH) QK_LOAD(nq0, nq1, nk0, nk1, c0 + 16);

        u32 a[2][4];
#pragma unroll
        for (int rm = 0; rm < 2; rm++) {
            int n0 = n_base + rm * 16;
            a[rm][0] = sq2[ctid * 136 + n0 + gid];
            a[rm][1] = sq2[ctid * 136 + n0 + gid + 8];
            a[rm][2] = sq2[(ctid + 4) * 136 + n0 + gid];
            a[rm][3] = sq2[(ctid + 4) * 136 + n0 + gid + 8];
        }
#pragma unroll
        for (int f = 0; f < 8; f++) {
            u32 bf[2];
            bf[0] = sk2[ctid * 136 + m_base + f * 8 + gid];
            bf[1] = sk2[(ctid + 4) * 136 + m_base + f * 8 + gid];
            mma_bf16(acc[0][f], a[0], bf);
            mma_bf16(acc[1][f], a[1], bf);
        }
        __syncthreads();

        pq0 = nq0; pq1 = nq1; pk0 = nk0; pk1 = nk1;
    }

    const float scale = 0.0625f;
    u32* Ab = A + ((size_t)b * NN + nb) * (MM / 2) + (mb >> 1);
#pragma unroll
    for (int rm = 0; rm < 2; rm++) {
#pragma unroll
        for (int f = 0; f < 8; f++) {
            int r0 = n_base + rm * 16 + gid;
            int m2 = (m_base + f * 8 + 2 * ctid) >> 1;
            float e0 = __expf(acc[rm][f][0] * scale);
            float e1 = __expf(acc[rm][f][1] * scale);
            float e2 = __expf(acc[rm][f][2] * scale);
            float e3 = __expf(acc[rm][f][3] * scale);
            Ab[(size_t)r0 * (MM / 2) + m2]       = pkbf(e0, e1);
            Ab[(size_t)(r0 + 8) * (MM / 2) + m2] = pkbf(e2, e3);
        }
    }
}

// ---------------------------------------------------------------------------
// Row sums of bf16 expE. One warp per row, 8 rows/block. grid: B*NN/8.
// ---------------------------------------------------------------------------
__global__ __launch_bounds__(256) void rowsum_kernel(
    const u32* __restrict__ A, float* __restrict__ rs)
{
    const int warp = threadIdx.x >> 5;
    const int lane = threadIdx.x & 31;
    const size_t row = (size_t)blockIdx.x * 8 + warp;
    const uint4* p = reinterpret_cast<const uint4*>(A + row * (MM / 2));

    float s = 0.f;
#pragma unroll
    for (int i = 0; i < 4; i++) {
        uint4 v = p[lane + 32 * i];
        float2 a = upbf(v.x), bq = upbf(v.y), c = upbf(v.z), d = upbf(v.w);
        s += (a.x + a.y) + (bq.x + bq.y) + (c.x + c.y) + (d.x + d.y);
    }
#pragma unroll
    for (int o = 16; o > 0; o >>= 1)
        s += __shfl_xor_sync(0xFFFFFFFFu, s, o);

    if (lane == 0) rs[row] = s;
}

// ---------------------------------------------------------------------------
// out = gamma * (V expE^T) / rowsum  (bf16 m16n8k16).
// grid: (NN/128=32, CCH/128=2, B=8)
// ---------------------------------------------------------------------------
__global__ __launch_bounds__(256, 2) void gemm_av_mma(
    const float* __restrict__ V, const u32* __restrict__ A,
    const float* __restrict__ rs,
    const float* __restrict__ gamma, float* __restrict__ out)
{
    const int nb = blockIdx.x * 128;
    const int cb = blockIdx.y * 128;
    const int b  = blockIdx.z;
    const int tid  = threadIdx.x;
    const int lane = tid & 31;
    const int w    = tid >> 5;
    const int gid  = lane >> 2;
    const int ctid = lane & 3;
    const int n_base = (w & 1) * 64;
    const int c_base = (w >> 1) * 32;

    __shared__ u32 sv2[8 * 136];
    __shared__ u32 sa2[8 * 136];

    float acc[2][8][4];
#pragma unroll
    for (int i = 0; i < 2; i++)
#pragma unroll
        for (int j = 0; j < 8; j++)
#pragma unroll
            for (int l = 0; l < 4; l++) acc[i][j][l] = 0.f;

    const float* Vb = V + (size_t)b * CCH * MM;
    const u32* Ab = A + (size_t)b * NN * (MM / 2);
    const float* rsb = rs + (size_t)b * NN;

    const int row0 = tid >> 2, f0 = tid & 3;
    const int row1 = row0 + 64;

    float4 pv0, pv1, nv0, nv1;
    uint2 pa0, pa1, na0, na1;

#define AV_LOAD(v0, v1, a0v, a1v, M0)                                                           \
    {                                                                                           \
        v0  = *reinterpret_cast<const float4*>(&Vb[(size_t)(cb + row0) * MM + (M0) + f0 * 4]);   \
        v1  = *reinterpret_cast<const float4*>(&Vb[(size_t)(cb + row1) * MM + (M0) + f0 * 4]);   \
        a0v = *reinterpret_cast<const uint2*>(&Ab[(size_t)(nb + row0) * (MM / 2) + ((M0) >> 1) + f0 * 2]); \
        a1v = *reinterpret_cast<const uint2*>(&Ab[(size_t)(nb + row1) * (MM / 2) + ((M0) >> 1) + f0 * 2]); \
    }

    AV_LOAD(pv0, pv1, pa0, pa1, 0);

    for (int m0 = 0; m0 < MM; m0 += 16) {
        sv2[(f0 * 2) * 136 + row0]     = pkbf(pv0.x, pv0.y);
        sv2[(f0 * 2 + 1) * 136 + row0] = pkbf(pv0.z, pv0.w);
        sv2[(f0 * 2) * 136 + row1]     = pkbf(pv1.x, pv1.y);
        sv2[(f0 * 2 + 1) * 136 + row1] = pkbf(pv1.z, pv1.w);
        sa2[(f0 * 2) * 136 + row0]     = pa0.x;
        sa2[(f0 * 2 + 1) * 136 + row0] = pa0.y;
        sa2[(f0 * 2) * 136 + row1]     = pa1.x;
        sa2[(f0 * 2 + 1) * 136 + row1] = pa1.y;
        __syncthreads();

        if (m0 + 16 < MM) AV_LOAD(nv0, nv1, na0, na1, m0 + 16);

        u32 a[2][4];
#pragma unroll
        for (int rm = 0; rm < 2; rm++) {
            int c0 = c_base + rm * 16;
            a[rm][0] = sv2[ctid * 136 + c0 + gid];
            a[rm][1] = sv2[ctid * 136 + c0 + gid + 8];
            a[rm][2] = sv2[(ctid + 4) * 136 + c0 + gid];
            a[rm][3] = sv2[(ctid + 4) * 136 + c0 + gid + 8];
        }
#pragma unroll
        for (int f = 0; f < 8; f++) {
            u32 bf[2];
            bf[0] = sa2[ctid * 136 + n_base + f * 8 + gid];
            bf[1] = sa2[(ctid + 4) * 136 + n_base + f * 8 + gid];
            mma_bf16(acc[0][f], a[0], bf);
            mma_bf16(acc[1][f], a[1], bf);
        }
        __syncthreads();

        pv0 = nv0; pv1 = nv1; pa0 = na0; pa1 = na1;
    }

    const float gm = gamma[0];
#pragma unroll
    for (int rm = 0; rm < 2; rm++) {
#pragma unroll
        for (int f = 0; f < 8; f++) {
            int c0 = cb + c_base + rm * 16 + gid;
            int nn2 = nb + n_base + f * 8 + 2 * ctid;
            float i0 = gm / rsb[nn2];
            float i1 = gm / rsb[nn2 + 1];
            float2 s0 = {acc[rm][f][0] * i0, acc[rm][f][1] * i1};
            float2 s1 = {acc[rm][f][2] * i0, acc[rm][f][3] * i1};
            *reinterpret_cast<float2*>(&out[((size_t)b * CCH + c0) * NN + nn2])     = s0;
            *reinterpret_cast<float2*>(&out[((size_t)b * CCH + c0 + 8) * NN + nn2]) = s1;
        }
    }
}

// ---------------------------------------------------------------------------
extern "C" void kernel_launch(void* const* d_in, const int* in_sizes, int n_in,
                              void* d_out, int out_size)
{
    const float* x        = (const float*)d_in[0];
    const float* y        = (const float*)d_in[1];
    const float* Wq       = (const float*)d_in[2];
    const float* bq       = (const float*)d_in[3];
    const float* gq_scale = (const float*)d_in[4];
    const float* gq_bias  = (const float*)d_in[5];
    const float* Wk       = (const float*)d_in[6];
    const float* bk       = (const float*)d_in[7];
    const float* gk_scale = (const float*)d_in[8];
    const float* gk_bias  = (const float*)d_in[9];
    const float* Wv       = (const float*)d_in[10];
    const float* bv       = (const float*)d_in[11];
    const float* gv_scale = (const float*)d_in[12];
    const float* gv_bias  = (const float*)d_in[13];
    const float* gamma    = (const float*)d_in[14];
    float* out = (float*)d_out;

    float *qp = nullptr, *kp = nullptr, *vp = nullptr, *rsp = nullptr;
    u32 *ap = nullptr, *xpp = nullptr, *wtp = nullptr, *wkp = nullptr, *wvp = nullptr;
    cudaGetSymbolAddress((void**)&qp, g_q);
    cudaGetSymbolAddress((void**)&kp, g_k);
    cudaGetSymbolAddress((void**)&vp, g_v);
    cudaGetSymbolAddress((void**)&rsp, g_rs);
    cudaGetSymbolAddress((void**)&ap, g_a);
    cudaGetSymbolAddress((void**)&xpp, g_xp);
    cudaGetSymbolAddress((void**)&wtp, g_wt3);
    cudaGetSymbolAddress((void**)&wkp, g_wk2);
    cudaGetSymbolAddress((void**)&wvp, g_wv2);

    xpack_kernel<<<(BATCH * 128 * NN + 255) / 256, 256>>>(x, xpp);
    transpose_w3<<<(9 * 128 * 256 + 255) / 256, 256>>>(Wq, wtp);
    transpose_w2<<<(4 * 256 * 256 + 255) / 256, 256>>>(Wk, Wv, wkp, wvp);

    conv_fused<<<768, 256>>>(wtp, xpp, bq, qp, wkp, wvp, y, bk, bv, kp, vp);

    gn_silu_kernel<<<BATCH * 64, 512>>>(kp, vp, gk_scale, gk_bias,
                                        gv_scale, gv_bias, MM);
    gn_silu_kernel<<<BATCH * 32, 512>>>(qp, nullptr, gq_scale, gq_bias,
                                        nullptr, nullptr, NN);

    gemm_qk_mma<<<dim3(MM / 128, NN / 128, BATCH), 256>>>(qp, kp, ap);
    rowsum_kernel<<<BATCH * NN / 8, 256>>>(ap, rsp);
    gemm_av_mma<<<dim3(NN / 128, CCH / 128, BATCH), 256>>>(vp, ap, rsp, gamma, out);
}